// round 12
// baseline (speedup 1.0000x reference)
#include <cuda_runtime.h>
#include <cstdint>
#include <math.h>

#define B_      8
#define M_      8
#define BM      64
#define SL      4096
#define P_      16
#define STRIDE_ 8
#define NP      511
#define DM      64
#define H_      8
#define DH      8
#define DFF     256
#define PRED    96
#define UP      35
#define NROW    (BM*NP)      // 32704
#define KTOT    (NP*DM)      // 32704
#define NSEG    32
#define SEG     1022

// ---------------- scratch ----------------
__device__ float g_z  [NROW*DM];
__device__ float g_q  [NROW*DM];
__device__ float g_k  [NROW*DM];
__device__ float g_v  [NROW*DM];
__device__ float g_ctx[NROW*DM];
__device__ float g_x1 [NROW*DM];
__device__ int   g_idxT[2*UP*NP];        // [e][u][l]
__device__ float g_sp [BM*H_*NP];
__device__ int   g_top[BM*H_*UP];
__device__ float g_pp [PRED*BM*NSEG];

__device__ __forceinline__ void fma4(float4& o, float s, const float4& b) {
    o.x += s * b.x; o.y += s * b.y; o.z += s * b.z; o.w += s * b.w;
}

// ---------------- threefry2x32 (bitwise JAX-compatible) ----------------
__device__ __forceinline__ uint32_t rotl32(uint32_t v, int r) {
    return (v << r) | (v >> (32 - r));
}

__device__ __forceinline__ void tf2x32(uint32_t k0, uint32_t k1,
                                       uint32_t& x0, uint32_t& x1) {
    uint32_t ks0 = k0, ks1 = k1, ks2 = k0 ^ k1 ^ 0x1BD11BDAu;
    const int ra[4] = {13, 15, 26, 6};
    const int rb[4] = {17, 29, 16, 24};
    x0 += ks0; x1 += ks1;
    #pragma unroll
    for (int i = 0; i < 4; i++) { x0 += x1; x1 = rotl32(x1, ra[i]); x1 ^= x0; }
    x0 += ks1; x1 += ks2 + 1u;
    #pragma unroll
    for (int i = 0; i < 4; i++) { x0 += x1; x1 = rotl32(x1, rb[i]); x1 ^= x0; }
    x0 += ks2; x1 += ks0 + 2u;
    #pragma unroll
    for (int i = 0; i < 4; i++) { x0 += x1; x1 = rotl32(x1, ra[i]); x1 ^= x0; }
    x0 += ks0; x1 += ks1 + 3u;
    #pragma unroll
    for (int i = 0; i < 4; i++) { x0 += x1; x1 = rotl32(x1, rb[i]); x1 ^= x0; }
    x0 += ks1; x1 += ks2 + 4u;
    #pragma unroll
    for (int i = 0; i < 4; i++) { x0 += x1; x1 = rotl32(x1, ra[i]); x1 ^= x0; }
    x0 += ks2; x1 += ks0 + 5u;
}

__device__ __forceinline__ uint32_t rbits17885(uint32_t k0, uint32_t k1, int j) {
    const int HALF = 8943;
    uint32_t x0, x1;
    if (j < HALF) {
        x0 = (uint32_t)j;
        x1 = (j < HALF - 1) ? (uint32_t)(j + HALF) : 0u;
        tf2x32(k0, k1, x0, x1);
        return x0;
    } else {
        x0 = (uint32_t)(j - HALF);
        x1 = (uint32_t)j;
        tf2x32(k0, k1, x0, x1);
        return x1;
    }
}

__global__ void rand_idx_kernel() {
    int j2 = blockIdx.x * blockDim.x + threadIdx.x;
    if (j2 >= 2 * NP * UP) return;
    int e = j2 / (NP * UP);
    int j = j2 % (NP * UP);
    uint32_t f0 = 0u, f1 = (uint32_t)e;
    tf2x32(0u, 1u, f0, f1);
    uint32_t a0 = 0u, a1 = 2u; tf2x32(f0, f1, a0, a1);
    uint32_t b0 = 1u, b1 = 3u; tf2x32(f0, f1, b0, b1);
    uint32_t hi = rbits17885(a0, b0, j);
    uint32_t lo = rbits17885(a1, b1, j);
    uint32_t off = ((hi % 511u) * 32u + (lo % 511u)) % 511u;
    int l = j / UP, u = j % UP;
    g_idxT[e * UP * NP + u * NP + l] = (int)off;
}

// ---------------- patch embedding ----------------
__global__ void patch_embed_kernel(const float* __restrict__ xe,
                                   const float* __restrict__ inW,
                                   const float* __restrict__ inb) {
    __shared__ float ps[16][17];
    __shared__ float ws[64][17];
    __shared__ float bs[64];
    int t = threadIdx.x;
    int r0 = blockIdx.x * 16;
    {
        int rr = t / 16, p = t % 16;
        int r = r0 + rr;
        int bm = r / NP, n = r % NP;
        int b = bm / M_, m = bm % M_;
        ps[rr][p] = xe[(b * SL + n * STRIDE_ + p) * M_ + m];
    }
    for (int i = t; i < 64 * P_; i += 256) ws[i / P_][i % P_] = inW[i];
    if (t < 64) bs[t] = inb[t];
    __syncthreads();
    int c = t % 64, q4 = t / 64;
    #pragma unroll
    for (int rr = q4 * 4; rr < q4 * 4 + 4; rr++) {
        float acc = bs[c];
        #pragma unroll
        for (int p = 0; p < P_; p++) acc += ws[c][p] * ps[rr][p];
        g_z[(r0 + rr) * DM + c] = acc;
    }
}

// ---------------- QKV GEMM ----------------
struct SmemG128 {
    float As[128][68];
    float Bs[64][68];
};

__global__ __launch_bounds__(256)
void qkv_kernel(const float* __restrict__ Wq, const float* __restrict__ bq,
                const float* __restrict__ Wk, const float* __restrict__ bk,
                const float* __restrict__ Wv, const float* __restrict__ bv) {
    extern __shared__ char smem_raw[];
    SmemG128* S = (SmemG128*)smem_raw;
    int t = threadIdx.x;
    int r0 = blockIdx.x * 128;
    int rows = NROW - r0; if (rows > 128) rows = 128;
    const float* W; const float* bias; float* out;
    if (blockIdx.y == 0)      { W = Wq; bias = bq; out = g_q; }
    else if (blockIdx.y == 1) { W = Wk; bias = bk; out = g_k; }
    else                      { W = Wv; bias = bv; out = g_v; }

    for (int i = t; i < 128 * 16; i += 256) {
        int row = i / 16, f4 = i % 16;
        float4 v = make_float4(0.f, 0.f, 0.f, 0.f);
        if (row < rows) v = *(const float4*)&g_z[(r0 + row) * DM + f4 * 4];
        *(float4*)&S->As[row][f4 * 4] = v;
    }
    {
        int c = t >> 2, ks0 = (t & 3) * 16;
        #pragma unroll
        for (int q = 0; q < 4; q++) {
            float4 wv = *(const float4*)&W[c * 64 + ks0 + q * 4];
            S->Bs[ks0 + q * 4 + 0][c] = wv.x;
            S->Bs[ks0 + q * 4 + 1][c] = wv.y;
            S->Bs[ks0 + q * 4 + 2][c] = wv.z;
            S->Bs[ks0 + q * 4 + 3][c] = wv.w;
        }
    }
    __syncthreads();
    int rg = t >> 4, cg = t & 15;
    float4 acc[8];
    #pragma unroll
    for (int r = 0; r < 8; r++) acc[r] = make_float4(0.f, 0.f, 0.f, 0.f);
    #pragma unroll
    for (int k = 0; k < 64; k += 4) {
        float4 b0 = *(float4*)&S->Bs[k + 0][cg * 4];
        float4 b1 = *(float4*)&S->Bs[k + 1][cg * 4];
        float4 b2 = *(float4*)&S->Bs[k + 2][cg * 4];
        float4 b3 = *(float4*)&S->Bs[k + 3][cg * 4];
        #pragma unroll
        for (int r = 0; r < 8; r++) {
            float4 a = *(float4*)&S->As[rg * 8 + r][k];
            fma4(acc[r], a.x, b0); fma4(acc[r], a.y, b1);
            fma4(acc[r], a.z, b2); fma4(acc[r], a.w, b3);
        }
    }
    float4 bb = *(const float4*)&bias[cg * 4];
    #pragma unroll
    for (int r = 0; r < 8; r++) {
        int row = rg * 8 + r;
        if (row < rows) {
            float4 o = make_float4(acc[r].x + bb.x, acc[r].y + bb.y,
                                   acc[r].z + bb.z, acc[r].w + bb.w);
            *(float4*)&out[(r0 + row) * DM + cg * 4] = o;
        }
    }
}

// ---------------- V mean + broadcast (one block per bm) ----------------
__global__ __launch_bounds__(256)
void vmean_bcast_kernel() {
    __shared__ float part[4][64];
    __shared__ float4 mean4[16];
    int bm = blockIdx.x;
    int t = threadIdx.x;
    int col = t & 63, slice = t >> 6;
    float s = 0.f;
    for (int l = slice; l < NP; l += 4) s += g_v[(bm * NP + l) * DM + col];
    part[slice][col] = s;
    __syncthreads();
    if (t < 64) {
        float v = (part[0][t] + part[1][t] + part[2][t] + part[3][t]) / (float)NP;
        ((float*)mean4)[t] = v;
    }
    __syncthreads();
    float4* gc4 = (float4*)g_ctx;
    long base = (long)bm * NP * 16;
    for (int i = t; i < NP * 16; i += 256)
        gc4[base + i] = mean4[i & 15];
}

// ---------------- sparsity scores (one block per bm,h; K loaded once) -----
__global__ __launch_bounds__(256)
void sparsity_kernel(int e) {
    __shared__ float4 klo[NP];
    __shared__ float4 khi[NP];
    int bh = blockIdx.x;
    int bm = bh / H_, h = bh % H_;
    int t = threadIdx.x;
    long rbase = (long)bm * NP;
    const int* idxT = g_idxT + e * UP * NP;

    const float4* gk4 = (const float4*)g_k;
    const float4* gq4 = (const float4*)g_q;
    for (int i = t; i < NP * 2; i += 256) {
        int l = i >> 1, half = i & 1;
        float4 v = gk4[(rbase + l) * 16 + h * 2 + half];
        if (half == 0) klo[l] = v; else khi[l] = v;
    }
    __syncthreads();

    for (int l = t; l < NP; l += 256) {
        long qb = (rbase + l) * 16 + h * 2;
        float4 q0 = gq4[qb], q1 = gq4[qb + 1];
        float mx = -INFINITY, sm = 0.f;
        #pragma unroll 7
        for (int u = 0; u < UP; u++) {
            int j = idxT[u * NP + l];            // coalesced across lanes
            float4 k0 = klo[j];
            float4 k1 = khi[j];
            float dot = q0.x*k0.x + q0.y*k0.y + q0.z*k0.z + q0.w*k0.w
                      + q1.x*k1.x + q1.y*k1.y + q1.z*k1.z + q1.w*k1.w;
            mx = fmaxf(mx, dot);
            sm += dot;
        }
        g_sp[bh * NP + l] = mx - sm / (float)NP;
    }
}

// ---------------- single-warp argmax top-35 ----------------
__global__ __launch_bounds__(32)
void argmax_kernel() {
    int bh = blockIdx.x;
    int lane = threadIdx.x;
    const float* sp = g_sp + bh * NP;
    float vals[16];
    #pragma unroll
    for (int jj = 0; jj < 16; jj++) {
        int l = lane + 32 * jj;
        vals[jj] = (l < NP) ? sp[l] : -INFINITY;
    }
    for (int it = 0; it < UP; it++) {
        float bv = -INFINITY; int bi = NP;
        #pragma unroll
        for (int jj = 0; jj < 16; jj++) {
            float v = vals[jj];
            if (v > bv) { bv = v; bi = lane + 32 * jj; }
        }
        #pragma unroll
        for (int off = 16; off; off >>= 1) {
            float ov = __shfl_xor_sync(0xffffffffu, bv, off);
            int   oi = __shfl_xor_sync(0xffffffffu, bi, off);
            if (ov > bv || (ov == bv && oi < bi)) { bv = ov; bi = oi; }
        }
        if (lane == 0) g_top[bh * UP + it] = bi;
        if ((bi & 31) == lane) {
            int tgt = bi >> 5;
            #pragma unroll
            for (int jj = 0; jj < 16; jj++)
                if (jj == tgt) vals[jj] = -INFINITY;
        }
    }
}

// ---------------- dense attention (dual-chain online softmax) ----------
__global__ __launch_bounds__(256)
void attn_dense_kernel() {
    __shared__ float4 klo[512];
    __shared__ float4 khi[512];
    __shared__ float4 vlo[512];
    __shared__ float4 vhi[512];
    __shared__ int   top[UP];
    int bm = blockIdx.x / H_, h = blockIdx.x % H_;
    int t = threadIdx.x, lane = t & 31, w = t >> 5;
    long rbase = (long)bm * NP;

    const float4* gk4 = (const float4*)g_k;
    const float4* gv4 = (const float4*)g_v;
    const float4* gq4 = (const float4*)g_q;
    for (int i = t; i < NP * 2; i += 256) {
        int l = i >> 1, half = i & 1;
        long src = (rbase + l) * 16 + h * 2 + half;
        float4 kv = gk4[src];
        float4 vv = gv4[src];
        if (half == 0) { klo[l] = kv; vlo[l] = vv; }
        else           { khi[l] = kv; vhi[l] = vv; }
    }
    if (t == 0) {
        float4 z = make_float4(0.f, 0.f, 0.f, 0.f);
        klo[511] = z; khi[511] = z; vlo[511] = z; vhi[511] = z;
    }
    if (t < UP) top[t] = g_top[blockIdx.x * UP + t];
    __syncthreads();

    float4* gc4 = (float4*)g_ctx;
    const float scale = 0.35355339059327373f;
    for (int i = w; i < UP; i += 8) {
        int l = top[i];
        long qb = (rbase + l) * 16 + h * 2;
        float4 q0 = gq4[qb], q1 = gq4[qb + 1];
        // two independent online-softmax chains (even/odd jj)
        float mA = -INFINITY, sumA = 0.f;
        float4 aA0 = make_float4(0.f,0.f,0.f,0.f), aA1 = make_float4(0.f,0.f,0.f,0.f);
        float mB = -INFINITY, sumB = 0.f;
        float4 aB0 = make_float4(0.f,0.f,0.f,0.f), aB1 = make_float4(0.f,0.f,0.f,0.f);
        #pragma unroll
        for (int jj = 0; jj < 16; jj += 2) {
            {   // chain A: jj (all j <= 479, always valid)
                int j = lane + 32 * jj;
                float4 k0 = klo[j], k1 = khi[j];
                float s = (q0.x*k0.x + q0.y*k0.y + q0.z*k0.z + q0.w*k0.w
                         + q1.x*k1.x + q1.y*k1.y + q1.z*k1.z + q1.w*k1.w) * scale;
                float mn = fmaxf(mA, s);
                float corr = __expf(mA - mn);
                float p    = __expf(s - mn);
                sumA = sumA * corr + p;
                float4 v0 = vlo[j], v1 = vhi[j];
                aA0.x = aA0.x * corr + p * v0.x; aA0.y = aA0.y * corr + p * v0.y;
                aA0.z = aA0.z * corr + p * v0.z; aA0.w = aA0.w * corr + p * v0.w;
                aA1.x = aA1.x * corr + p * v1.x; aA1.y = aA1.y * corr + p * v1.y;
                aA1.z = aA1.z * corr + p * v1.z; aA1.w = aA1.w * corr + p * v1.w;
                mA = mn;
            }
            {   // chain B: jj+1 (only j==511 invalid -> forced -INF)
                int j = lane + 32 * (jj + 1);
                float4 k0 = klo[j], k1 = khi[j];
                float s = (q0.x*k0.x + q0.y*k0.y + q0.z*k0.z + q0.w*k0.w
                         + q1.x*k1.x + q1.y*k1.y + q1.z*k1.z + q1.w*k1.w) * scale;
                if (jj + 1 == 15 && j == 511) s = -INFINITY;
                float mn = fmaxf(mB, s);
                float corr = __expf(mB - mn);
                float p    = __expf(s - mn);
                sumB = sumB * corr + p;
                float4 v0 = vlo[j], v1 = vhi[j];
                aB0.x = aB0.x * corr + p * v0.x; aB0.y = aB0.y * corr + p * v0.y;
                aB0.z = aB0.z * corr + p * v0.z; aB0.w = aB0.w * corr + p * v0.w;
                aB1.x = aB1.x * corr + p * v1.x; aB1.y = aB1.y * corr + p * v1.y;
                aB1.z = aB1.z * corr + p * v1.z; aB1.w = aB1.w * corr + p * v1.w;
                mB = mn;
            }
        }
        // merge the two chains
        float m = fmaxf(mA, mB);
        float cA = __expf(mA - m), cB = __expf(mB - m);
        float sum = sumA * cA + sumB * cB;
        float4 a0, a1;
        a0.x = aA0.x * cA + aB0.x * cB; a0.y = aA0.y * cA + aB0.y * cB;
        a0.z = aA0.z * cA + aB0.z * cB; a0.w = aA0.w * cA + aB0.w * cB;
        a1.x = aA1.x * cA + aB1.x * cB; a1.y = aA1.y * cA + aB1.y * cB;
        a1.z = aA1.z * cA + aB1.z * cB; a1.w = aA1.w * cA + aB1.w * cB;
        // warp reduce (global max rescale then sum)
        float M = m;
        #pragma unroll
        for (int off = 16; off; off >>= 1)
            M = fmaxf(M, __shfl_xor_sync(0xffffffffu, M, off));
        float c = __expf(m - M);
        sum *= c;
        a0.x *= c; a0.y *= c; a0.z *= c; a0.w *= c;
        a1.x *= c; a1.y *= c; a1.z *= c; a1.w *= c;
        #pragma unroll
        for (int off = 16; off; off >>= 1) {
            sum  += __shfl_xor_sync(0xffffffffu, sum, off);
            a0.x += __shfl_xor_sync(0xffffffffu, a0.x, off);
            a0.y += __shfl_xor_sync(0xffffffffu, a0.y, off);
            a0.z += __shfl_xor_sync(0xffffffffu, a0.z, off);
            a0.w += __shfl_xor_sync(0xffffffffu, a0.w, off);
            a1.x += __shfl_xor_sync(0xffffffffu, a1.x, off);
            a1.y += __shfl_xor_sync(0xffffffffu, a1.y, off);
            a1.z += __shfl_xor_sync(0xffffffffu, a1.z, off);
            a1.w += __shfl_xor_sync(0xffffffffu, a1.w, off);
        }
        if (lane == 0) {
            float inv = 1.f / sum;
            gc4[qb]     = make_float4(a0.x*inv, a0.y*inv, a0.z*inv, a0.w*inv);
            gc4[qb + 1] = make_float4(a1.x*inv, a1.y*inv, a1.z*inv, a1.w*inv);
        }
    }
}

// ---------------- Wo GEMM + residual + LN1 ----------------
__global__ __launch_bounds__(256)
void wo_ln1_kernel(const float* __restrict__ Wo, const float* __restrict__ bo,
                   const float* __restrict__ g1, const float* __restrict__ b1) {
    extern __shared__ char smem_raw[];
    SmemG128* S = (SmemG128*)smem_raw;
    int t = threadIdx.x;
    int r0 = blockIdx.x * 128;
    int rows = NROW - r0; if (rows > 128) rows = 128;

    for (int i = t; i < 128 * 16; i += 256) {
        int row = i / 16, f4 = i % 16;
        float4 v = make_float4(0.f, 0.f, 0.f, 0.f);
        if (row < rows) v = *(const float4*)&g_ctx[(r0 + row) * DM + f4 * 4];
        *(float4*)&S->As[row][f4 * 4] = v;
    }
    {
        int c = t >> 2, ks0 = (t & 3) * 16;
        #pragma unroll
        for (int q = 0; q < 4; q++) {
            float4 wv = *(const float4*)&Wo[c * 64 + ks0 + q * 4];
            S->Bs[ks0 + q * 4 + 0][c] = wv.x;
            S->Bs[ks0 + q * 4 + 1][c] = wv.y;
            S->Bs[ks0 + q * 4 + 2][c] = wv.z;
            S->Bs[ks0 + q * 4 + 3][c] = wv.w;
        }
    }
    __syncthreads();
    int rg = t >> 4, cg = t & 15;
    float4 acc[8];
    #pragma unroll
    for (int r = 0; r < 8; r++) acc[r] = make_float4(0.f, 0.f, 0.f, 0.f);
    #pragma unroll
    for (int k = 0; k < 64; k += 4) {
        float4 b0 = *(float4*)&S->Bs[k + 0][cg * 4];
        float4 b1v = *(float4*)&S->Bs[k + 1][cg * 4];
        float4 b2 = *(float4*)&S->Bs[k + 2][cg * 4];
        float4 b3 = *(float4*)&S->Bs[k + 3][cg * 4];
        #pragma unroll
        for (int r = 0; r < 8; r++) {
            float4 a = *(float4*)&S->As[rg * 8 + r][k];
            fma4(acc[r], a.x, b0); fma4(acc[r], a.y, b1v);
            fma4(acc[r], a.z, b2); fma4(acc[r], a.w, b3);
        }
    }
    __syncthreads();
    float4 bb = *(const float4*)&bo[cg * 4];
    #pragma unroll
    for (int r = 0; r < 8; r++) {
        int row = rg * 8 + r;
        if (row < rows) {
            float4 z = *(const float4*)&g_z[(r0 + row) * DM + cg * 4];
            S->As[row][cg * 4 + 0] = acc[r].x + bb.x + z.x;
            S->As[row][cg * 4 + 1] = acc[r].y + bb.y + z.y;
            S->As[row][cg * 4 + 2] = acc[r].z + bb.z + z.z;
            S->As[row][cg * 4 + 3] = acc[r].w + bb.w + z.w;
        }
    }
    __syncthreads();
    int lane = t & 31, w2 = t >> 5;
    for (int rr = 0; rr < 16; rr++) {
        int row = w2 * 16 + rr;
        if (row >= rows) break;
        float v0 = S->As[row][lane], v1 = S->As[row][lane + 32];
        float s = v0 + v1;
        #pragma unroll
        for (int o = 16; o; o >>= 1) s += __shfl_xor_sync(0xffffffffu, s, o);
        float mu = s / 64.f;
        float d0 = v0 - mu, d1 = v1 - mu;
        float vv = d0 * d0 + d1 * d1;
        #pragma unroll
        for (int o = 16; o; o >>= 1) vv += __shfl_xor_sync(0xffffffffu, vv, o);
        float inv = rsqrtf(vv / 64.f + 1e-5f);
        g_x1[(r0 + row) * DM + lane]      = d0 * inv * g1[lane]      + b1[lane];
        g_x1[(r0 + row) * DM + lane + 32] = d1 * inv * g1[lane + 32] + b1[lane + 32];
    }
}

// ---------------- fused FFN + residual + LN2 (two-phase) ----------------
struct SmemFFN {
    float xs[64][68];
    float wb[64][68];
    float ys[64][260];
};

__global__ __launch_bounds__(256)
void ffn_ln2_kernel(const float* __restrict__ W1, const float* __restrict__ b1f,
                    const float* __restrict__ W2, const float* __restrict__ b2f,
                    const float* __restrict__ g2, const float* __restrict__ bb2) {
    extern __shared__ char smem_raw[];
    SmemFFN* S = (SmemFFN*)smem_raw;
    int t = threadIdx.x;
    int r0 = blockIdx.x * 64;
    int rg = t >> 4, cg = t & 15;
    int cw = t >> 2, ks0 = (t & 3) * 16;

    for (int i = t; i < 64 * 16; i += 256) {
        int row = i / 16, f4 = i % 16;
        *(float4*)&S->xs[row][f4 * 4] = *(const float4*)&g_x1[(r0 + row) * DM + f4 * 4];
    }

    for (int cc = 0; cc < 4; cc++) {
        __syncthreads();
        #pragma unroll
        for (int q = 0; q < 4; q++) {
            float4 wv = *(const float4*)&W1[(cc * 64 + cw) * 64 + ks0 + q * 4];
            S->wb[ks0 + q * 4 + 0][cw] = wv.x;
            S->wb[ks0 + q * 4 + 1][cw] = wv.y;
            S->wb[ks0 + q * 4 + 2][cw] = wv.z;
            S->wb[ks0 + q * 4 + 3][cw] = wv.w;
        }
        __syncthreads();
        float4 acc[4];
        #pragma unroll
        for (int r = 0; r < 4; r++) acc[r] = make_float4(0.f, 0.f, 0.f, 0.f);
        #pragma unroll
        for (int k = 0; k < 64; k += 4) {
            float4 b0 = *(float4*)&S->wb[k + 0][cg * 4];
            float4 b1 = *(float4*)&S->wb[k + 1][cg * 4];
            float4 b2 = *(float4*)&S->wb[k + 2][cg * 4];
            float4 b3 = *(float4*)&S->wb[k + 3][cg * 4];
            #pragma unroll
            for (int r = 0; r < 4; r++) {
                float4 a = *(float4*)&S->xs[rg * 4 + r][k];
                fma4(acc[r], a.x, b0); fma4(acc[r], a.y, b1);
                fma4(acc[r], a.z, b2); fma4(acc[r], a.w, b3);
            }
        }
        float4 bb = *(const float4*)&b1f[cc * 64 + cg * 4];
        #pragma unroll
        for (int r = 0; r < 4; r++) {
            float x0 = acc[r].x + bb.x, x1 = acc[r].y + bb.y;
            float x2 = acc[r].z + bb.z, x3 = acc[r].w + bb.w;
            float4 y;
            y.x = x0 * 0.5f * (1.f + erff(x0 * 0.7071067811865476f));
            y.y = x1 * 0.5f * (1.f + erff(x1 * 0.7071067811865476f));
            y.z = x2 * 0.5f * (1.f + erff(x2 * 0.7071067811865476f));
            y.w = x3 * 0.5f * (1.f + erff(x3 * 0.7071067811865476f));
            *(float4*)&S->ys[rg * 4 + r][cc * 64 + cg * 4] = y;
        }
    }

    float4 acc2[4];
    #pragma unroll
    for (int r = 0; r < 4; r++) acc2[r] = make_float4(0.f, 0.f, 0.f, 0.f);
    for (int kc = 0; kc < 4; kc++) {
        __syncthreads();
        #pragma unroll
        for (int q = 0; q < 4; q++) {
            float4 wv = *(const float4*)&W2[cw * 256 + kc * 64 + ks0 + q * 4];
            S->wb[ks0 + q * 4 + 0][cw] = wv.x;
            S->wb[ks0 + q * 4 + 1][cw] = wv.y;
            S->wb[ks0 + q * 4 + 2][cw] = wv.z;
            S->wb[ks0 + q * 4 + 3][cw] = wv.w;
        }
        __syncthreads();
        #pragma unroll
        for (int k = 0; k < 64; k += 4) {
            float4 b0 = *(float4*)&S->wb[k + 0][cg * 4];
            float4 b1 = *(float4*)&S->wb[k + 1][cg * 4];
            float4 b2 = *(float4*)&S->wb[k + 2][cg * 4];
            float4 b3 = *(float4*)&S->wb[k + 3][cg * 4];
            #pragma unroll
            for (int r = 0; r < 4; r++) {
                float4 a = *(float4*)&S->ys[rg * 4 + r][kc * 64 + k];
                fma4(acc2[r], a.x, b0); fma4(acc2[r], a.y, b1);
                fma4(acc2[r], a.z, b2); fma4(acc2[r], a.w, b3);
            }
        }
    }
    __syncthreads();
    {
        float4 bb = *(const float4*)&b2f[cg * 4];
        #pragma unroll
        for (int r = 0; r < 4; r++) {
            int row = rg * 4 + r;
            S->xs[row][cg * 4 + 0] += acc2[r].x + bb.x;
            S->xs[row][cg * 4 + 1] += acc2[r].y + bb.y;
            S->xs[row][cg * 4 + 2] += acc2[r].z + bb.z;
            S->xs[row][cg * 4 + 3] += acc2[r].w + bb.w;
        }
    }
    __syncthreads();
    int lane = t & 31, w2 = t >> 5;
    #pragma unroll
    for (int rr = 0; rr < 8; rr++) {
        int row = w2 * 8 + rr;
        float v0 = S->xs[row][lane], v1 = S->xs[row][lane + 32];
        float s = v0 + v1;
        #pragma unroll
        for (int o = 16; o; o >>= 1) s += __shfl_xor_sync(0xffffffffu, s, o);
        float mu = s / 64.f;
        float d0 = v0 - mu, d1 = v1 - mu;
        float vv = d0 * d0 + d1 * d1;
        #pragma unroll
        for (int o = 16; o; o >>= 1) vv += __shfl_xor_sync(0xffffffffu, vv, o);
        float inv = rsqrtf(vv / 64.f + 1e-5f);
        g_z[(r0 + row) * DM + lane]      = d0 * inv * g2[lane]      + bb2[lane];
        g_z[(r0 + row) * DM + lane + 32] = d1 * inv * g2[lane + 32] + bb2[lane + 32];
    }
}

// ---------------- final LN ----------------
__global__ void final_ln_kernel(const float* __restrict__ gf, const float* __restrict__ bf) {
    int t = threadIdx.x, lane = t & 31, w = t >> 5;
    int r = blockIdx.x * 8 + w;
    float v0 = g_z[r * DM + lane], v1 = g_z[r * DM + lane + 32];
    float s = v0 + v1;
    #pragma unroll
    for (int o = 16; o; o >>= 1) s += __shfl_xor_sync(0xffffffffu, s, o);
    float mu = s / 64.f;
    float d0 = v0 - mu, d1 = v1 - mu;
    float vv = d0 * d0 + d1 * d1;
    #pragma unroll
    for (int o = 16; o; o >>= 1) vv += __shfl_xor_sync(0xffffffffu, vv, o);
    float inv = rsqrtf(vv / 64.f + 1e-5f);
    g_z[r * DM + lane]      = d0 * inv * gf[lane]      + bf[lane];
    g_z[r * DM + lane + 32] = d1 * inv * gf[lane + 32] + bf[lane + 32];
}

// ---------------- output projection ----------------
__global__ void proj_partial_kernel(const float* __restrict__ outW) {
    int seg = blockIdx.x;
    int bg  = blockIdx.y;
    __shared__ float zc[8][SEG];
    int t = threadIdx.x, lane = t & 31, w = t >> 5;
    int k0 = seg * SEG;
    for (int i = t; i < 8 * SEG; i += 256) {
        int bmo = i / SEG, kk = i % SEG;
        zc[bmo][kk] = g_z[(bg * 8 + bmo) * KTOT + k0 + kk];
    }
    __syncthreads();
    for (int p = w; p < PRED; p += 8) {
        float acc[8] = {0.f, 0.f, 0.f, 0.f, 0.f, 0.f, 0.f, 0.f};
        for (int kk = lane; kk < SEG; kk += 32) {
            float ww = outW[p * KTOT + k0 + kk];
            #pragma unroll
            for (int bmo = 0; bmo < 8; bmo++) acc[bmo] += ww * zc[bmo][kk];
        }
        #pragma unroll
        for (int bmo = 0; bmo < 8; bmo++) {
            #pragma unroll
            for (int o = 16; o; o >>= 1)
                acc[bmo] += __shfl_xor_sync(0xffffffffu, acc[bmo], o);
        }
        if (lane == 0) {
            #pragma unroll
            for (int bmo = 0; bmo < 8; bmo++)
                g_pp[(p * BM + bg * 8 + bmo) * NSEG + seg] = acc[bmo];
        }
    }
}

__global__ void proj_reduce_kernel(const float* __restrict__ outb, float* __restrict__ out) {
    int i = blockIdx.x * 256 + threadIdx.x;
    if (i >= PRED * BM) return;
    int p = i / BM, bm = i % BM;
    float s = outb[p];
    #pragma unroll
    for (int seg = 0; seg < NSEG; seg++) s += g_pp[(p * BM + bm) * NSEG + seg];
    int b = bm / M_, m = bm % M_;
    out[(b * PRED + p) * M_ + m] = s;
}

// ---------------- launch ----------------
extern "C" void kernel_launch(void* const* d_in, const int* in_sizes, int n_in,
                              void* d_out, int out_size) {
    const float* x_enc = (const float*)d_in[0];
    const float* in_W  = (const float*)d_in[4];
    const float* in_b  = (const float*)d_in[5];
    const float* Wq    = (const float*)d_in[6];
    const float* bq    = (const float*)d_in[7];
    const float* Wk    = (const float*)d_in[8];
    const float* bk    = (const float*)d_in[9];
    const float* Wv    = (const float*)d_in[10];
    const float* bv    = (const float*)d_in[11];
    const float* Wo    = (const float*)d_in[12];
    const float* bo    = (const float*)d_in[13];
    const float* c1_W  = (const float*)d_in[14];
    const float* c1_b  = (const float*)d_in[15];
    const float* c2_W  = (const float*)d_in[16];
    const float* c2_b  = (const float*)d_in[17];
    const float* ln1_g = (const float*)d_in[18];
    const float* ln1_b = (const float*)d_in[19];
    const float* ln2_g = (const float*)d_in[20];
    const float* ln2_b = (const float*)d_in[21];
    const float* lnf_g = (const float*)d_in[22];
    const float* lnf_b = (const float*)d_in[23];
    const float* out_W = (const float*)d_in[24];
    const float* out_b = (const float*)d_in[25];
    float* out = (float*)d_out;

    const int smemG = sizeof(SmemG128);
    const int smemF = sizeof(SmemFFN);
    cudaFuncSetAttribute(qkv_kernel,    cudaFuncAttributeMaxDynamicSharedMemorySize, smemG);
    cudaFuncSetAttribute(wo_ln1_kernel, cudaFuncAttributeMaxDynamicSharedMemorySize, smemG);
    cudaFuncSetAttribute(ffn_ln2_kernel,cudaFuncAttributeMaxDynamicSharedMemorySize, smemF);

    rand_idx_kernel<<<(2 * NP * UP + 255) / 256, 256>>>();
    patch_embed_kernel<<<NROW / 16, 256>>>(x_enc, in_W, in_b);

    for (int e = 0; e < 2; e++) {
        qkv_kernel<<<dim3(256, 3), 256, smemG>>>(Wq + e * DM * DM, bq + e * DM,
                                                 Wk + e * DM * DM, bk + e * DM,
                                                 Wv + e * DM * DM, bv + e * DM);
        sparsity_kernel<<<BM * H_, 256>>>(e);
        argmax_kernel<<<BM * H_, 32>>>();
        vmean_bcast_kernel<<<BM, 256>>>();
        attn_dense_kernel<<<BM * H_, 256>>>();
        wo_ln1_kernel<<<256, 256, smemG>>>(Wo + e * DM * DM, bo + e * DM,
                                           ln1_g + e * DM, ln1_b + e * DM);
        ffn_ln2_kernel<<<NROW / 64, 256, smemF>>>(c1_W + e * DFF * DM, c1_b + e * DFF,
                                                  c2_W + e * DM * DFF, c2_b + e * DM,
                                                  ln2_g + e * DM, ln2_b + e * DM);
    }

    final_ln_kernel<<<NROW / 8, 256>>>(lnf_g, lnf_b);
    proj_partial_kernel<<<dim3(NSEG, 8), 256>>>(out_W);
    proj_reduce_kernel<<<(PRED * BM + 255) / 256, 256>>>(out_b, out);
}

// round 13
// speedup vs baseline: 1.1071x; 1.1071x over previous
#include <cuda_runtime.h>
#include <cstdint>
#include <math.h>

#define B_      8
#define M_      8
#define BM      64
#define SL      4096
#define P_      16
#define STRIDE_ 8
#define NP      511
#define DM      64
#define H_      8
#define DH      8
#define DFF     256
#define PRED    96
#define UP      35
#define NROW    (BM*NP)      // 32704
#define KTOT    (NP*DM)      // 32704
#define NSEG    32
#define SEG     1022

// ---------------- scratch ----------------
__device__ float g_z  [NROW*DM];
__device__ float g_q  [NROW*DM];
__device__ float g_k  [NROW*DM];
__device__ float g_v  [NROW*DM];
__device__ float g_ctx[NROW*DM];
__device__ float g_x1 [NROW*DM];
__device__ int   g_idxT[2*UP*NP];        // [e][u][l]
__device__ float g_sp [BM*H_*NP];
__device__ int   g_top[BM*H_*UP];
__device__ float g_vmean[BM*DM];
__device__ float g_pp [PRED*BM*NSEG];

__device__ __forceinline__ void fma4(float4& o, float s, const float4& b) {
    o.x += s * b.x; o.y += s * b.y; o.z += s * b.z; o.w += s * b.w;
}

// ---------------- threefry2x32 (bitwise JAX-compatible) ----------------
__device__ __forceinline__ uint32_t rotl32(uint32_t v, int r) {
    return (v << r) | (v >> (32 - r));
}

__device__ __forceinline__ void tf2x32(uint32_t k0, uint32_t k1,
                                       uint32_t& x0, uint32_t& x1) {
    uint32_t ks0 = k0, ks1 = k1, ks2 = k0 ^ k1 ^ 0x1BD11BDAu;
    const int ra[4] = {13, 15, 26, 6};
    const int rb[4] = {17, 29, 16, 24};
    x0 += ks0; x1 += ks1;
    #pragma unroll
    for (int i = 0; i < 4; i++) { x0 += x1; x1 = rotl32(x1, ra[i]); x1 ^= x0; }
    x0 += ks1; x1 += ks2 + 1u;
    #pragma unroll
    for (int i = 0; i < 4; i++) { x0 += x1; x1 = rotl32(x1, rb[i]); x1 ^= x0; }
    x0 += ks2; x1 += ks0 + 2u;
    #pragma unroll
    for (int i = 0; i < 4; i++) { x0 += x1; x1 = rotl32(x1, ra[i]); x1 ^= x0; }
    x0 += ks0; x1 += ks1 + 3u;
    #pragma unroll
    for (int i = 0; i < 4; i++) { x0 += x1; x1 = rotl32(x1, rb[i]); x1 ^= x0; }
    x0 += ks1; x1 += ks2 + 4u;
    #pragma unroll
    for (int i = 0; i < 4; i++) { x0 += x1; x1 = rotl32(x1, ra[i]); x1 ^= x0; }
    x0 += ks2; x1 += ks0 + 5u;
}

__device__ __forceinline__ uint32_t rbits17885(uint32_t k0, uint32_t k1, int j) {
    const int HALF = 8943;
    uint32_t x0, x1;
    if (j < HALF) {
        x0 = (uint32_t)j;
        x1 = (j < HALF - 1) ? (uint32_t)(j + HALF) : 0u;
        tf2x32(k0, k1, x0, x1);
        return x0;
    } else {
        x0 = (uint32_t)(j - HALF);
        x1 = (uint32_t)j;
        tf2x32(k0, k1, x0, x1);
        return x1;
    }
}

__global__ void rand_idx_kernel() {
    int j2 = blockIdx.x * blockDim.x + threadIdx.x;
    if (j2 >= 2 * NP * UP) return;
    int e = j2 / (NP * UP);
    int j = j2 % (NP * UP);
    uint32_t f0 = 0u, f1 = (uint32_t)e;
    tf2x32(0u, 1u, f0, f1);
    uint32_t a0 = 0u, a1 = 2u; tf2x32(f0, f1, a0, a1);
    uint32_t b0 = 1u, b1 = 3u; tf2x32(f0, f1, b0, b1);
    uint32_t hi = rbits17885(a0, b0, j);
    uint32_t lo = rbits17885(a1, b1, j);
    uint32_t off = ((hi % 511u) * 32u + (lo % 511u)) % 511u;
    int l = j / UP, u = j % UP;
    g_idxT[e * UP * NP + u * NP + l] = (int)off;
}

// ---------------- patch embedding ----------------
__global__ void patch_embed_kernel(const float* __restrict__ xe,
                                   const float* __restrict__ inW,
                                   const float* __restrict__ inb) {
    __shared__ float ps[16][17];
    __shared__ float ws[64][17];
    __shared__ float bs[64];
    int t = threadIdx.x;
    int r0 = blockIdx.x * 16;
    {
        int rr = t / 16, p = t % 16;
        int r = r0 + rr;
        int bm = r / NP, n = r % NP;
        int b = bm / M_, m = bm % M_;
        ps[rr][p] = xe[(b * SL + n * STRIDE_ + p) * M_ + m];
    }
    for (int i = t; i < 64 * P_; i += 256) ws[i / P_][i % P_] = inW[i];
    if (t < 64) bs[t] = inb[t];
    __syncthreads();
    int c = t % 64, q4 = t / 64;
    #pragma unroll
    for (int rr = q4 * 4; rr < q4 * 4 + 4; rr++) {
        float acc = bs[c];
        #pragma unroll
        for (int p = 0; p < P_; p++) acc += ws[c][p] * ps[rr][p];
        g_z[(r0 + rr) * DM + c] = acc;
    }
}

// ---------------- QKV GEMM ----------------
struct SmemG128 {
    float As[128][68];
    float Bs[64][68];
};

__global__ __launch_bounds__(256)
void qkv_kernel(const float* __restrict__ Wq, const float* __restrict__ bq,
                const float* __restrict__ Wk, const float* __restrict__ bk,
                const float* __restrict__ Wv, const float* __restrict__ bv) {
    extern __shared__ char smem_raw[];
    SmemG128* S = (SmemG128*)smem_raw;
    int t = threadIdx.x;
    int r0 = blockIdx.x * 128;
    int rows = NROW - r0; if (rows > 128) rows = 128;
    const float* W; const float* bias; float* out;
    if (blockIdx.y == 0)      { W = Wq; bias = bq; out = g_q; }
    else if (blockIdx.y == 1) { W = Wk; bias = bk; out = g_k; }
    else                      { W = Wv; bias = bv; out = g_v; }

    for (int i = t; i < 128 * 16; i += 256) {
        int row = i / 16, f4 = i % 16;
        float4 v = make_float4(0.f, 0.f, 0.f, 0.f);
        if (row < rows) v = *(const float4*)&g_z[(r0 + row) * DM + f4 * 4];
        *(float4*)&S->As[row][f4 * 4] = v;
    }
    {
        int c = t >> 2, ks0 = (t & 3) * 16;
        #pragma unroll
        for (int q = 0; q < 4; q++) {
            float4 wv = *(const float4*)&W[c * 64 + ks0 + q * 4];
            S->Bs[ks0 + q * 4 + 0][c] = wv.x;
            S->Bs[ks0 + q * 4 + 1][c] = wv.y;
            S->Bs[ks0 + q * 4 + 2][c] = wv.z;
            S->Bs[ks0 + q * 4 + 3][c] = wv.w;
        }
    }
    __syncthreads();
    int rg = t >> 4, cg = t & 15;
    float4 acc[8];
    #pragma unroll
    for (int r = 0; r < 8; r++) acc[r] = make_float4(0.f, 0.f, 0.f, 0.f);
    #pragma unroll
    for (int k = 0; k < 64; k += 4) {
        float4 b0 = *(float4*)&S->Bs[k + 0][cg * 4];
        float4 b1 = *(float4*)&S->Bs[k + 1][cg * 4];
        float4 b2 = *(float4*)&S->Bs[k + 2][cg * 4];
        float4 b3 = *(float4*)&S->Bs[k + 3][cg * 4];
        #pragma unroll
        for (int r = 0; r < 8; r++) {
            float4 a = *(float4*)&S->As[rg * 8 + r][k];
            fma4(acc[r], a.x, b0); fma4(acc[r], a.y, b1);
            fma4(acc[r], a.z, b2); fma4(acc[r], a.w, b3);
        }
    }
    float4 bb = *(const float4*)&bias[cg * 4];
    #pragma unroll
    for (int r = 0; r < 8; r++) {
        int row = rg * 8 + r;
        if (row < rows) {
            float4 o = make_float4(acc[r].x + bb.x, acc[r].y + bb.y,
                                   acc[r].z + bb.z, acc[r].w + bb.w);
            *(float4*)&out[(r0 + row) * DM + cg * 4] = o;
        }
    }
}

// ---------------- V mean per bm ----------------
__global__ __launch_bounds__(256)
void vmean_kernel() {
    __shared__ float part[4][64];
    int bm = blockIdx.x;
    int t = threadIdx.x;
    int col = t & 63, slice = t >> 6;
    float s = 0.f;
    for (int l = slice; l < NP; l += 4) s += g_v[(bm * NP + l) * DM + col];
    part[slice][col] = s;
    __syncthreads();
    if (t < 64) {
        float v = (part[0][t] + part[1][t] + part[2][t] + part[3][t]) / (float)NP;
        g_vmean[bm * DM + t] = v;
    }
}

// ---------------- broadcast vmean into g_ctx ----------------
__global__ __launch_bounds__(256)
void bcast_kernel() {
    int i = blockIdx.x * 256 + threadIdx.x;
    int row = i >> 4, f4 = i & 15;
    int bm = row / NP;
    ((float4*)g_ctx)[i] = ((const float4*)g_vmean)[bm * 16 + f4];
}

// ---------------- sparsity scores (one block per bm,h; K loaded once) -----
__global__ __launch_bounds__(256)
void sparsity_kernel(int e) {
    __shared__ float4 klo[NP];
    __shared__ float4 khi[NP];
    int bh = blockIdx.x;
    int bm = bh / H_, h = bh % H_;
    int t = threadIdx.x;
    long rbase = (long)bm * NP;
    const int* idxT = g_idxT + e * UP * NP;

    const float4* gk4 = (const float4*)g_k;
    const float4* gq4 = (const float4*)g_q;
    for (int i = t; i < NP * 2; i += 256) {
        int l = i >> 1, half = i & 1;
        float4 v = gk4[(rbase + l) * 16 + h * 2 + half];
        if (half == 0) klo[l] = v; else khi[l] = v;
    }
    __syncthreads();

    for (int l = t; l < NP; l += 256) {
        long qb = (rbase + l) * 16 + h * 2;
        float4 q0 = gq4[qb], q1 = gq4[qb + 1];
        float mx = -INFINITY, sm = 0.f;
        #pragma unroll 7
        for (int u = 0; u < UP; u++) {
            int j = idxT[u * NP + l];            // coalesced across lanes
            float4 k0 = klo[j];
            float4 k1 = khi[j];
            float dot = q0.x*k0.x + q0.y*k0.y + q0.z*k0.z + q0.w*k0.w
                      + q1.x*k1.x + q1.y*k1.y + q1.z*k1.z + q1.w*k1.w;
            mx = fmaxf(mx, dot);
            sm += dot;
        }
        g_sp[bh * NP + l] = mx - sm / (float)NP;
    }
}

// ---------------- single-warp argmax top-35 ----------------
__global__ __launch_bounds__(32)
void argmax_kernel() {
    int bh = blockIdx.x;
    int lane = threadIdx.x;
    const float* sp = g_sp + bh * NP;
    float vals[16];
    #pragma unroll
    for (int jj = 0; jj < 16; jj++) {
        int l = lane + 32 * jj;
        vals[jj] = (l < NP) ? sp[l] : -INFINITY;
    }
    for (int it = 0; it < UP; it++) {
        float bv = -INFINITY; int bi = NP;
        #pragma unroll
        for (int jj = 0; jj < 16; jj++) {
            float v = vals[jj];
            if (v > bv) { bv = v; bi = lane + 32 * jj; }
        }
        #pragma unroll
        for (int off = 16; off; off >>= 1) {
            float ov = __shfl_xor_sync(0xffffffffu, bv, off);
            int   oi = __shfl_xor_sync(0xffffffffu, bi, off);
            if (ov > bv || (ov == bv && oi < bi)) { bv = ov; bi = oi; }
        }
        if (lane == 0) g_top[bh * UP + it] = bi;
        if ((bi & 31) == lane) {
            int tgt = bi >> 5;
            #pragma unroll
            for (int jj = 0; jj < 16; jj++)
                if (jj == tgt) vals[jj] = -INFINITY;
        }
    }
}

// ---------------- dense attention for selected queries (online softmax) ----
__global__ __launch_bounds__(256)
void attn_dense_kernel() {
    __shared__ float4 klo[NP];
    __shared__ float4 khi[NP];
    __shared__ float4 vlo[NP];
    __shared__ float4 vhi[NP];
    __shared__ int   top[UP];
    int bm = blockIdx.x / H_, h = blockIdx.x % H_;
    int t = threadIdx.x, lane = t & 31, w = t >> 5;
    long rbase = (long)bm * NP;

    const float4* gk4 = (const float4*)g_k;
    const float4* gv4 = (const float4*)g_v;
    const float4* gq4 = (const float4*)g_q;
    for (int i = t; i < NP * 2; i += 256) {
        int l = i >> 1, half = i & 1;
        long src = (rbase + l) * 16 + h * 2 + half;
        float4 kv = gk4[src];
        float4 vv = gv4[src];
        if (half == 0) { klo[l] = kv; vlo[l] = vv; }
        else           { khi[l] = kv; vhi[l] = vv; }
    }
    if (t < UP) top[t] = g_top[blockIdx.x * UP + t];
    __syncthreads();

    float4* gc4 = (float4*)g_ctx;
    const float scale = 0.35355339059327373f;
    for (int i = w; i < UP; i += 8) {
        int l = top[i];
        long qb = (rbase + l) * 16 + h * 2;
        float4 q0 = gq4[qb], q1 = gq4[qb + 1];
        float m = -INFINITY, sum = 0.f;
        float4 a0 = make_float4(0.f, 0.f, 0.f, 0.f);
        float4 a1 = make_float4(0.f, 0.f, 0.f, 0.f);
        #pragma unroll 4
        for (int jj = 0; jj < 16; jj++) {
            int j = lane + 32 * jj;
            float s;
            if (j < NP) {
                float4 k0 = klo[j];
                float4 k1 = khi[j];
                s = (q0.x*k0.x + q0.y*k0.y + q0.z*k0.z + q0.w*k0.w
                   + q1.x*k1.x + q1.y*k1.y + q1.z*k1.z + q1.w*k1.w) * scale;
            } else s = -INFINITY;
            float mn = fmaxf(m, s);
            float corr = __expf(m - mn);
            float p    = __expf(s - mn);
            sum = sum * corr + p;
            if (j < NP) {
                float4 v0 = vlo[j];
                float4 v1 = vhi[j];
                a0.x = a0.x * corr + p * v0.x; a0.y = a0.y * corr + p * v0.y;
                a0.z = a0.z * corr + p * v0.z; a0.w = a0.w * corr + p * v0.w;
                a1.x = a1.x * corr + p * v1.x; a1.y = a1.y * corr + p * v1.y;
                a1.z = a1.z * corr + p * v1.z; a1.w = a1.w * corr + p * v1.w;
            } else {
                a0.x *= corr; a0.y *= corr; a0.z *= corr; a0.w *= corr;
                a1.x *= corr; a1.y *= corr; a1.z *= corr; a1.w *= corr;
            }
            m = mn;
        }
        float M = m;
        #pragma unroll
        for (int off = 16; off; off >>= 1)
            M = fmaxf(M, __shfl_xor_sync(0xffffffffu, M, off));
        float c = __expf(m - M);
        sum *= c;
        a0.x *= c; a0.y *= c; a0.z *= c; a0.w *= c;
        a1.x *= c; a1.y *= c; a1.z *= c; a1.w *= c;
        #pragma unroll
        for (int off = 16; off; off >>= 1) {
            sum  += __shfl_xor_sync(0xffffffffu, sum, off);
            a0.x += __shfl_xor_sync(0xffffffffu, a0.x, off);
            a0.y += __shfl_xor_sync(0xffffffffu, a0.y, off);
            a0.z += __shfl_xor_sync(0xffffffffu, a0.z, off);
            a0.w += __shfl_xor_sync(0xffffffffu, a0.w, off);
            a1.x += __shfl_xor_sync(0xffffffffu, a1.x, off);
            a1.y += __shfl_xor_sync(0xffffffffu, a1.y, off);
            a1.z += __shfl_xor_sync(0xffffffffu, a1.z, off);
            a1.w += __shfl_xor_sync(0xffffffffu, a1.w, off);
        }
        if (lane == 0) {
            float inv = 1.f / sum;
            gc4[qb]     = make_float4(a0.x*inv, a0.y*inv, a0.z*inv, a0.w*inv);
            gc4[qb + 1] = make_float4(a1.x*inv, a1.y*inv, a1.z*inv, a1.w*inv);
        }
    }
}

// ---------------- Wo GEMM + residual + LN1 ----------------
__global__ __launch_bounds__(256)
void wo_ln1_kernel(const float* __restrict__ Wo, const float* __restrict__ bo,
                   const float* __restrict__ g1, const float* __restrict__ b1) {
    extern __shared__ char smem_raw[];
    SmemG128* S = (SmemG128*)smem_raw;
    int t = threadIdx.x;
    int r0 = blockIdx.x * 128;
    int rows = NROW - r0; if (rows > 128) rows = 128;

    for (int i = t; i < 128 * 16; i += 256) {
        int row = i / 16, f4 = i % 16;
        float4 v = make_float4(0.f, 0.f, 0.f, 0.f);
        if (row < rows) v = *(const float4*)&g_ctx[(r0 + row) * DM + f4 * 4];
        *(float4*)&S->As[row][f4 * 4] = v;
    }
    {
        int c = t >> 2, ks0 = (t & 3) * 16;
        #pragma unroll
        for (int q = 0; q < 4; q++) {
            float4 wv = *(const float4*)&Wo[c * 64 + ks0 + q * 4];
            S->Bs[ks0 + q * 4 + 0][c] = wv.x;
            S->Bs[ks0 + q * 4 + 1][c] = wv.y;
            S->Bs[ks0 + q * 4 + 2][c] = wv.z;
            S->Bs[ks0 + q * 4 + 3][c] = wv.w;
        }
    }
    __syncthreads();
    int rg = t >> 4, cg = t & 15;
    float4 acc[8];
    #pragma unroll
    for (int r = 0; r < 8; r++) acc[r] = make_float4(0.f, 0.f, 0.f, 0.f);
    #pragma unroll
    for (int k = 0; k < 64; k += 4) {
        float4 b0 = *(float4*)&S->Bs[k + 0][cg * 4];
        float4 b1v = *(float4*)&S->Bs[k + 1][cg * 4];
        float4 b2 = *(float4*)&S->Bs[k + 2][cg * 4];
        float4 b3 = *(float4*)&S->Bs[k + 3][cg * 4];
        #pragma unroll
        for (int r = 0; r < 8; r++) {
            float4 a = *(float4*)&S->As[rg * 8 + r][k];
            fma4(acc[r], a.x, b0); fma4(acc[r], a.y, b1v);
            fma4(acc[r], a.z, b2); fma4(acc[r], a.w, b3);
        }
    }
    __syncthreads();
    float4 bb = *(const float4*)&bo[cg * 4];
    #pragma unroll
    for (int r = 0; r < 8; r++) {
        int row = rg * 8 + r;
        if (row < rows) {
            float4 z = *(const float4*)&g_z[(r0 + row) * DM + cg * 4];
            S->As[row][cg * 4 + 0] = acc[r].x + bb.x + z.x;
            S->As[row][cg * 4 + 1] = acc[r].y + bb.y + z.y;
            S->As[row][cg * 4 + 2] = acc[r].z + bb.z + z.z;
            S->As[row][cg * 4 + 3] = acc[r].w + bb.w + z.w;
        }
    }
    __syncthreads();
    int lane = t & 31, w2 = t >> 5;
    for (int rr = 0; rr < 16; rr++) {
        int row = w2 * 16 + rr;
        if (row >= rows) break;
        float v0 = S->As[row][lane], v1 = S->As[row][lane + 32];
        float s = v0 + v1;
        #pragma unroll
        for (int o = 16; o; o >>= 1) s += __shfl_xor_sync(0xffffffffu, s, o);
        float mu = s / 64.f;
        float d0 = v0 - mu, d1 = v1 - mu;
        float vv = d0 * d0 + d1 * d1;
        #pragma unroll
        for (int o = 16; o; o >>= 1) vv += __shfl_xor_sync(0xffffffffu, vv, o);
        float inv = rsqrtf(vv / 64.f + 1e-5f);
        g_x1[(r0 + row) * DM + lane]      = d0 * inv * g1[lane]      + b1[lane];
        g_x1[(r0 + row) * DM + lane + 32] = d1 * inv * g1[lane + 32] + b1[lane + 32];
    }
}

// ---------------- fused FFN + residual + LN2 (two-phase) ----------------
struct SmemFFN {
    float xs[64][68];
    float wb[64][68];
    float ys[64][260];
};

__global__ __launch_bounds__(256)
void ffn_ln2_kernel(const float* __restrict__ W1, const float* __restrict__ b1f,
                    const float* __restrict__ W2, const float* __restrict__ b2f,
                    const float* __restrict__ g2, const float* __restrict__ bb2) {
    extern __shared__ char smem_raw[];
    SmemFFN* S = (SmemFFN*)smem_raw;
    int t = threadIdx.x;
    int r0 = blockIdx.x * 64;
    int rg = t >> 4, cg = t & 15;
    int cw = t >> 2, ks0 = (t & 3) * 16;

    for (int i = t; i < 64 * 16; i += 256) {
        int row = i / 16, f4 = i % 16;
        *(float4*)&S->xs[row][f4 * 4] = *(const float4*)&g_x1[(r0 + row) * DM + f4 * 4];
    }

    for (int cc = 0; cc < 4; cc++) {
        __syncthreads();
        #pragma unroll
        for (int q = 0; q < 4; q++) {
            float4 wv = *(const float4*)&W1[(cc * 64 + cw) * 64 + ks0 + q * 4];
            S->wb[ks0 + q * 4 + 0][cw] = wv.x;
            S->wb[ks0 + q * 4 + 1][cw] = wv.y;
            S->wb[ks0 + q * 4 + 2][cw] = wv.z;
            S->wb[ks0 + q * 4 + 3][cw] = wv.w;
        }
        __syncthreads();
        float4 acc[4];
        #pragma unroll
        for (int r = 0; r < 4; r++) acc[r] = make_float4(0.f, 0.f, 0.f, 0.f);
        #pragma unroll
        for (int k = 0; k < 64; k += 4) {
            float4 b0 = *(float4*)&S->wb[k + 0][cg * 4];
            float4 b1 = *(float4*)&S->wb[k + 1][cg * 4];
            float4 b2 = *(float4*)&S->wb[k + 2][cg * 4];
            float4 b3 = *(float4*)&S->wb[k + 3][cg * 4];
            #pragma unroll
            for (int r = 0; r < 4; r++) {
                float4 a = *(float4*)&S->xs[rg * 4 + r][k];
                fma4(acc[r], a.x, b0); fma4(acc[r], a.y, b1);
                fma4(acc[r], a.z, b2); fma4(acc[r], a.w, b3);
            }
        }
        float4 bb = *(const float4*)&b1f[cc * 64 + cg * 4];
        #pragma unroll
        for (int r = 0; r < 4; r++) {
            float x0 = acc[r].x + bb.x, x1 = acc[r].y + bb.y;
            float x2 = acc[r].z + bb.z, x3 = acc[r].w + bb.w;
            float4 y;
            y.x = x0 * 0.5f * (1.f + erff(x0 * 0.7071067811865476f));
            y.y = x1 * 0.5f * (1.f + erff(x1 * 0.7071067811865476f));
            y.z = x2 * 0.5f * (1.f + erff(x2 * 0.7071067811865476f));
            y.w = x3 * 0.5f * (1.f + erff(x3 * 0.7071067811865476f));
            *(float4*)&S->ys[rg * 4 + r][cc * 64 + cg * 4] = y;
        }
    }

    float4 acc2[4];
    #pragma unroll
    for (int r = 0; r < 4; r++) acc2[r] = make_float4(0.f, 0.f, 0.f, 0.f);
    for (int kc = 0; kc < 4; kc++) {
        __syncthreads();
        #pragma unroll
        for (int q = 0; q < 4; q++) {
            float4 wv = *(const float4*)&W2[cw * 256 + kc * 64 + ks0 + q * 4];
            S->wb[ks0 + q * 4 + 0][cw] = wv.x;
            S->wb[ks0 + q * 4 + 1][cw] = wv.y;
            S->wb[ks0 + q * 4 + 2][cw] = wv.z;
            S->wb[ks0 + q * 4 + 3][cw] = wv.w;
        }
        __syncthreads();
        #pragma unroll
        for (int k = 0; k < 64; k += 4) {
            float4 b0 = *(float4*)&S->wb[k + 0][cg * 4];
            float4 b1 = *(float4*)&S->wb[k + 1][cg * 4];
            float4 b2 = *(float4*)&S->wb[k + 2][cg * 4];
            float4 b3 = *(float4*)&S->wb[k + 3][cg * 4];
            #pragma unroll
            for (int r = 0; r < 4; r++) {
                float4 a = *(float4*)&S->ys[rg * 4 + r][kc * 64 + k];
                fma4(acc2[r], a.x, b0); fma4(acc2[r], a.y, b1);
                fma4(acc2[r], a.z, b2); fma4(acc2[r], a.w, b3);
            }
        }
    }
    __syncthreads();
    {
        float4 bb = *(const float4*)&b2f[cg * 4];
        #pragma unroll
        for (int r = 0; r < 4; r++) {
            int row = rg * 4 + r;
            S->xs[row][cg * 4 + 0] += acc2[r].x + bb.x;
            S->xs[row][cg * 4 + 1] += acc2[r].y + bb.y;
            S->xs[row][cg * 4 + 2] += acc2[r].z + bb.z;
            S->xs[row][cg * 4 + 3] += acc2[r].w + bb.w;
        }
    }
    __syncthreads();
    int lane = t & 31, w2 = t >> 5;
    #pragma unroll
    for (int rr = 0; rr < 8; rr++) {
        int row = w2 * 8 + rr;
        float v0 = S->xs[row][lane], v1 = S->xs[row][lane + 32];
        float s = v0 + v1;
        #pragma unroll
        for (int o = 16; o; o >>= 1) s += __shfl_xor_sync(0xffffffffu, s, o);
        float mu = s / 64.f;
        float d0 = v0 - mu, d1 = v1 - mu;
        float vv = d0 * d0 + d1 * d1;
        #pragma unroll
        for (int o = 16; o; o >>= 1) vv += __shfl_xor_sync(0xffffffffu, vv, o);
        float inv = rsqrtf(vv / 64.f + 1e-5f);
        g_z[(r0 + row) * DM + lane]      = d0 * inv * g2[lane]      + bb2[lane];
        g_z[(r0 + row) * DM + lane + 32] = d1 * inv * g2[lane + 32] + bb2[lane + 32];
    }
}

// ---------------- final LN ----------------
__global__ void final_ln_kernel(const float* __restrict__ gf, const float* __restrict__ bf) {
    int t = threadIdx.x, lane = t & 31, w = t >> 5;
    int r = blockIdx.x * 8 + w;
    float v0 = g_z[r * DM + lane], v1 = g_z[r * DM + lane + 32];
    float s = v0 + v1;
    #pragma unroll
    for (int o = 16; o; o >>= 1) s += __shfl_xor_sync(0xffffffffu, s, o);
    float mu = s / 64.f;
    float d0 = v0 - mu, d1 = v1 - mu;
    float vv = d0 * d0 + d1 * d1;
    #pragma unroll
    for (int o = 16; o; o >>= 1) vv += __shfl_xor_sync(0xffffffffu, vv, o);
    float inv = rsqrtf(vv / 64.f + 1e-5f);
    g_z[r * DM + lane]      = d0 * inv * gf[lane]      + bf[lane];
    g_z[r * DM + lane + 32] = d1 * inv * gf[lane + 32] + bf[lane + 32];
}

// ---------------- output projection ----------------
__global__ void proj_partial_kernel(const float* __restrict__ outW) {
    int seg = blockIdx.x;
    int bg  = blockIdx.y;
    __shared__ float zc[8][SEG];
    int t = threadIdx.x, lane = t & 31, w = t >> 5;
    int k0 = seg * SEG;
    for (int i = t; i < 8 * SEG; i += 256) {
        int bmo = i / SEG, kk = i % SEG;
        zc[bmo][kk] = g_z[(bg * 8 + bmo) * KTOT + k0 + kk];
    }
    __syncthreads();
    for (int p = w; p < PRED; p += 8) {
        float acc[8] = {0.f, 0.f, 0.f, 0.f, 0.f, 0.f, 0.f, 0.f};
        for (int kk = lane; kk < SEG; kk += 32) {
            float ww = outW[p * KTOT + k0 + kk];
            #pragma unroll
            for (int bmo = 0; bmo < 8; bmo++) acc[bmo] += ww * zc[bmo][kk];
        }
        #pragma unroll
        for (int bmo = 0; bmo < 8; bmo++) {
            #pragma unroll
            for (int o = 16; o; o >>= 1)
                acc[bmo] += __shfl_xor_sync(0xffffffffu, acc[bmo], o);
        }
        if (lane == 0) {
            #pragma unroll
            for (int bmo = 0; bmo < 8; bmo++)
                g_pp[(p * BM + bg * 8 + bmo) * NSEG + seg] = acc[bmo];
        }
    }
}

__global__ void proj_reduce_kernel(const float* __restrict__ outb, float* __restrict__ out) {
    int i = blockIdx.x * 256 + threadIdx.x;
    if (i >= PRED * BM) return;
    int p = i / BM, bm = i % BM;
    float s = outb[p];
    #pragma unroll
    for (int seg = 0; seg < NSEG; seg++) s += g_pp[(p * BM + bm) * NSEG + seg];
    int b = bm / M_, m = bm % M_;
    out[(b * PRED + p) * M_ + m] = s;
}

// ---------------- launch ----------------
extern "C" void kernel_launch(void* const* d_in, const int* in_sizes, int n_in,
                              void* d_out, int out_size) {
    const float* x_enc = (const float*)d_in[0];
    const float* in_W  = (const float*)d_in[4];
    const float* in_b  = (const float*)d_in[5];
    const float* Wq    = (const float*)d_in[6];
    const float* bq    = (const float*)d_in[7];
    const float* Wk    = (const float*)d_in[8];
    const float* bk    = (const float*)d_in[9];
    const float* Wv    = (const float*)d_in[10];
    const float* bv    = (const float*)d_in[11];
    const float* Wo    = (const float*)d_in[12];
    const float* bo    = (const float*)d_in[13];
    const float* c1_W  = (const float*)d_in[14];
    const float* c1_b  = (const float*)d_in[15];
    const float* c2_W  = (const float*)d_in[16];
    const float* c2_b  = (const float*)d_in[17];
    const float* ln1_g = (const float*)d_in[18];
    const float* ln1_b = (const float*)d_in[19];
    const float* ln2_g = (const float*)d_in[20];
    const float* ln2_b = (const float*)d_in[21];
    const float* lnf_g = (const float*)d_in[22];
    const float* lnf_b = (const float*)d_in[23];
    const float* out_W = (const float*)d_in[24];
    const float* out_b = (const float*)d_in[25];
    float* out = (float*)d_out;

    const int smemG = sizeof(SmemG128);
    const int smemF = sizeof(SmemFFN);
    cudaFuncSetAttribute(qkv_kernel,    cudaFuncAttributeMaxDynamicSharedMemorySize, smemG);
    cudaFuncSetAttribute(wo_ln1_kernel, cudaFuncAttributeMaxDynamicSharedMemorySize, smemG);
    cudaFuncSetAttribute(ffn_ln2_kernel,cudaFuncAttributeMaxDynamicSharedMemorySize, smemF);

    // one-time side stream + events (host resources only; same captured work every call)
    static cudaStream_t s2 = nullptr;
    static cudaEvent_t evFork = nullptr, evIdx = nullptr;
    static cudaEvent_t evQ[2] = {nullptr, nullptr}, evV[2] = {nullptr, nullptr};
    if (s2 == nullptr) {
        cudaStreamCreateWithFlags(&s2, cudaStreamNonBlocking);
        cudaEventCreateWithFlags(&evFork, cudaEventDisableTiming);
        cudaEventCreateWithFlags(&evIdx,  cudaEventDisableTiming);
        for (int e = 0; e < 2; e++) {
            cudaEventCreateWithFlags(&evQ[e], cudaEventDisableTiming);
            cudaEventCreateWithFlags(&evV[e], cudaEventDisableTiming);
        }
    }

    // fork s2 from main stream
    cudaEventRecord(evFork, 0);
    cudaStreamWaitEvent(s2, evFork, 0);

    // s2: threefry indices (independent of patch embed)
    rand_idx_kernel<<<(2 * NP * UP + 255) / 256, 256, 0, s2>>>();
    cudaEventRecord(evIdx, s2);

    // main: patch embedding
    patch_embed_kernel<<<NROW / 16, 256>>>(x_enc, in_W, in_b);
    cudaStreamWaitEvent(0, evIdx, 0);   // sparsity (main) needs g_idxT

    for (int e = 0; e < 2; e++) {
        qkv_kernel<<<dim3(256, 3), 256, smemG>>>(Wq + e * DM * DM, bq + e * DM,
                                                 Wk + e * DM * DM, bk + e * DM,
                                                 Wv + e * DM * DM, bv + e * DM);
        cudaEventRecord(evQ[e], 0);

        // s2: V-path (vmean + broadcast) concurrent with K/Q-path on main
        cudaStreamWaitEvent(s2, evQ[e], 0);
        vmean_kernel<<<BM, 256, 0, s2>>>();
        bcast_kernel<<<NROW * 16 / 256, 256, 0, s2>>>();
        cudaEventRecord(evV[e], s2);

        // main: K/Q-path
        sparsity_kernel<<<BM * H_, 256>>>(e);
        argmax_kernel<<<BM * H_, 32>>>();

        // join: attention overwrites top rows after broadcast filled all rows
        cudaStreamWaitEvent(0, evV[e], 0);
        attn_dense_kernel<<<BM * H_, 256>>>();
        wo_ln1_kernel<<<256, 256, smemG>>>(Wo + e * DM * DM, bo + e * DM,
                                           ln1_g + e * DM, ln1_b + e * DM);
        ffn_ln2_kernel<<<NROW / 64, 256, smemF>>>(c1_W + e * DFF * DM, c1_b + e * DFF,
                                                  c2_W + e * DM * DFF, c2_b + e * DM,
                                                  ln2_g + e * DM, ln2_b + e * DM);
    }

    final_ln_kernel<<<NROW / 8, 256>>>(lnf_g, lnf_b);
    proj_partial_kernel<<<dim3(NSEG, 8), 256>>>(out_W);
    proj_reduce_kernel<<<(PRED * BM + 255) / 256, 256>>>(out_b, out);
}

// round 15
// speedup vs baseline: 1.2461x; 1.1256x over previous
#include <cuda_runtime.h>
#include <cstdint>
#include <math.h>

#define B_      8
#define M_      8
#define BM      64
#define SL      4096
#define P_      16
#define STRIDE_ 8
#define NP      511
#define DM      64
#define H_      8
#define DH      8
#define DFF     256
#define PRED    96
#define UP      35
#define NROW    (BM*NP)      // 32704
#define KTOT    (NP*DM)      // 32704
#define NSEG    32
#define SEG     1022

// ---------------- scratch ----------------
__device__ float g_z  [NROW*DM];
__device__ float g_q  [NROW*DM];
__device__ float g_k  [NROW*DM];
__device__ float g_v  [NROW*DM];
__device__ float g_ctx[NROW*DM];
__device__ float g_x1 [NROW*DM];
__device__ int   g_idxT[2*UP*NP];        // [e][u][l]
__device__ float g_sp [BM*H_*NP];
__device__ int   g_top[BM*H_*UP];
__device__ float g_vmean[BM*DM];
__device__ float g_pp [PRED*BM*NSEG];

__device__ __forceinline__ void fma4(float4& o, float s, const float4& b) {
    o.x += s * b.x; o.y += s * b.y; o.z += s * b.z; o.w += s * b.w;
}

// ---------------- tf32 mma helpers ----------------
__device__ __forceinline__ uint32_t tf32cvt(float v) {
    uint32_t r;
    asm("cvt.rna.tf32.f32 %0, %1;" : "=r"(r) : "f"(v));
    return r;
}

__device__ __forceinline__ void mma_tf32(float& c0, float& c1, float& c2, float& c3,
                                         uint32_t a0, uint32_t a1, uint32_t a2, uint32_t a3,
                                         uint32_t b0, uint32_t b1) {
    asm volatile(
        "mma.sync.aligned.m16n8k8.row.col.f32.tf32.tf32.f32 "
        "{%0,%1,%2,%3},{%4,%5,%6,%7},{%8,%9},{%0,%1,%2,%3};"
        : "+f"(c0), "+f"(c1), "+f"(c2), "+f"(c3)
        : "r"(a0), "r"(a1), "r"(a2), "r"(a3), "r"(b0), "r"(b1));
}

// ---------------- threefry2x32 (bitwise JAX-compatible) ----------------
__device__ __forceinline__ uint32_t rotl32(uint32_t v, int r) {
    return (v << r) | (v >> (32 - r));
}

__device__ __forceinline__ void tf2x32(uint32_t k0, uint32_t k1,
                                       uint32_t& x0, uint32_t& x1) {
    uint32_t ks0 = k0, ks1 = k1, ks2 = k0 ^ k1 ^ 0x1BD11BDAu;
    const int ra[4] = {13, 15, 26, 6};
    const int rb[4] = {17, 29, 16, 24};
    x0 += ks0; x1 += ks1;
    #pragma unroll
    for (int i = 0; i < 4; i++) { x0 += x1; x1 = rotl32(x1, ra[i]); x1 ^= x0; }
    x0 += ks1; x1 += ks2 + 1u;
    #pragma unroll
    for (int i = 0; i < 4; i++) { x0 += x1; x1 = rotl32(x1, rb[i]); x1 ^= x0; }
    x0 += ks2; x1 += ks0 + 2u;
    #pragma unroll
    for (int i = 0; i < 4; i++) { x0 += x1; x1 = rotl32(x1, ra[i]); x1 ^= x0; }
    x0 += ks0; x1 += ks1 + 3u;
    #pragma unroll
    for (int i = 0; i < 4; i++) { x0 += x1; x1 = rotl32(x1, rb[i]); x1 ^= x0; }
    x0 += ks1; x1 += ks2 + 4u;
    #pragma unroll
    for (int i = 0; i < 4; i++) { x0 += x1; x1 = rotl32(x1, ra[i]); x1 ^= x0; }
    x0 += ks2; x1 += ks0 + 5u;
}

__device__ __forceinline__ uint32_t rbits17885(uint32_t k0, uint32_t k1, int j) {
    const int HALF = 8943;
    uint32_t x0, x1;
    if (j < HALF) {
        x0 = (uint32_t)j;
        x1 = (j < HALF - 1) ? (uint32_t)(j + HALF) : 0u;
        tf2x32(k0, k1, x0, x1);
        return x0;
    } else {
        x0 = (uint32_t)(j - HALF);
        x1 = (uint32_t)j;
        tf2x32(k0, k1, x0, x1);
        return x1;
    }
}

__global__ void rand_idx_kernel() {
    int j2 = blockIdx.x * blockDim.x + threadIdx.x;
    if (j2 >= 2 * NP * UP) return;
    int e = j2 / (NP * UP);
    int j = j2 % (NP * UP);
    uint32_t f0 = 0u, f1 = (uint32_t)e;
    tf2x32(0u, 1u, f0, f1);
    uint32_t a0 = 0u, a1 = 2u; tf2x32(f0, f1, a0, a1);
    uint32_t b0 = 1u, b1 = 3u; tf2x32(f0, f1, b0, b1);
    uint32_t hi = rbits17885(a0, b0, j);
    uint32_t lo = rbits17885(a1, b1, j);
    uint32_t off = ((hi % 511u) * 32u + (lo % 511u)) % 511u;
    int l = j / UP, u = j % UP;
    g_idxT[e * UP * NP + u * NP + l] = (int)off;
}

// ---------------- patch embedding ----------------
__global__ void patch_embed_kernel(const float* __restrict__ xe,
                                   const float* __restrict__ inW,
                                   const float* __restrict__ inb) {
    __shared__ float ps[16][17];
    __shared__ float ws[64][17];
    __shared__ float bs[64];
    int t = threadIdx.x;
    int r0 = blockIdx.x * 16;
    {
        int rr = t / 16, p = t % 16;
        int r = r0 + rr;
        int bm = r / NP, n = r % NP;
        int b = bm / M_, m = bm % M_;
        ps[rr][p] = xe[(b * SL + n * STRIDE_ + p) * M_ + m];
    }
    for (int i = t; i < 64 * P_; i += 256) ws[i / P_][i % P_] = inW[i];
    if (t < 64) bs[t] = inb[t];
    __syncthreads();
    int c = t % 64, q4 = t / 64;
    #pragma unroll
    for (int rr = q4 * 4; rr < q4 * 4 + 4; rr++) {
        float acc = bs[c];
        #pragma unroll
        for (int p = 0; p < P_; p++) acc += ws[c][p] * ps[rr][p];
        g_z[(r0 + rr) * DM + c] = acc;
    }
}

// ---------------- QKV GEMM ----------------
struct SmemG128 {
    float As[128][68];
    float Bs[64][68];
};

__global__ __launch_bounds__(256)
void qkv_kernel(const float* __restrict__ Wq, const float* __restrict__ bq,
                const float* __restrict__ Wk, const float* __restrict__ bk,
                const float* __restrict__ Wv, const float* __restrict__ bv) {
    extern __shared__ char smem_raw[];
    SmemG128* S = (SmemG128*)smem_raw;
    int t = threadIdx.x;
    int r0 = blockIdx.x * 128;
    int rows = NROW - r0; if (rows > 128) rows = 128;
    const float* W; const float* bias; float* out;
    if (blockIdx.y == 0)      { W = Wq; bias = bq; out = g_q; }
    else if (blockIdx.y == 1) { W = Wk; bias = bk; out = g_k; }
    else                      { W = Wv; bias = bv; out = g_v; }

    for (int i = t; i < 128 * 16; i += 256) {
        int row = i / 16, f4 = i % 16;
        float4 v = make_float4(0.f, 0.f, 0.f, 0.f);
        if (row < rows) v = *(const float4*)&g_z[(r0 + row) * DM + f4 * 4];
        *(float4*)&S->As[row][f4 * 4] = v;
    }
    {
        int c = t >> 2, ks0 = (t & 3) * 16;
        #pragma unroll
        for (int q = 0; q < 4; q++) {
            float4 wv = *(const float4*)&W[c * 64 + ks0 + q * 4];
            S->Bs[ks0 + q * 4 + 0][c] = wv.x;
            S->Bs[ks0 + q * 4 + 1][c] = wv.y;
            S->Bs[ks0 + q * 4 + 2][c] = wv.z;
            S->Bs[ks0 + q * 4 + 3][c] = wv.w;
        }
    }
    __syncthreads();
    int rg = t >> 4, cg = t & 15;
    float4 acc[8];
    #pragma unroll
    for (int r = 0; r < 8; r++) acc[r] = make_float4(0.f, 0.f, 0.f, 0.f);
    #pragma unroll
    for (int k = 0; k < 64; k += 4) {
        float4 b0 = *(float4*)&S->Bs[k + 0][cg * 4];
        float4 b1 = *(float4*)&S->Bs[k + 1][cg * 4];
        float4 b2 = *(float4*)&S->Bs[k + 2][cg * 4];
        float4 b3 = *(float4*)&S->Bs[k + 3][cg * 4];
        #pragma unroll
        for (int r = 0; r < 8; r++) {
            float4 a = *(float4*)&S->As[rg * 8 + r][k];
            fma4(acc[r], a.x, b0); fma4(acc[r], a.y, b1);
            fma4(acc[r], a.z, b2); fma4(acc[r], a.w, b3);
        }
    }
    float4 bb = *(const float4*)&bias[cg * 4];
    #pragma unroll
    for (int r = 0; r < 8; r++) {
        int row = rg * 8 + r;
        if (row < rows) {
            float4 o = make_float4(acc[r].x + bb.x, acc[r].y + bb.y,
                                   acc[r].z + bb.z, acc[r].w + bb.w);
            *(float4*)&out[(r0 + row) * DM + cg * 4] = o;
        }
    }
}

// ---------------- V mean per bm ----------------
__global__ __launch_bounds__(256)
void vmean_kernel() {
    __shared__ float part[4][64];
    int bm = blockIdx.x;
    int t = threadIdx.x;
    int col = t & 63, slice = t >> 6;
    float s = 0.f;
    for (int l = slice; l < NP; l += 4) s += g_v[(bm * NP + l) * DM + col];
    part[slice][col] = s;
    __syncthreads();
    if (t < 64) {
        float v = (part[0][t] + part[1][t] + part[2][t] + part[3][t]) / (float)NP;
        g_vmean[bm * DM + t] = v;
    }
}

// ---------------- broadcast vmean into g_ctx ----------------
__global__ __launch_bounds__(256)
void bcast_kernel() {
    int i = blockIdx.x * 256 + threadIdx.x;
    int row = i >> 4, f4 = i & 15;
    int bm = row / NP;
    ((float4*)g_ctx)[i] = ((const float4*)g_vmean)[bm * 16 + f4];
}

// ---------------- sparsity scores ----------------
__global__ __launch_bounds__(256)
void sparsity_kernel(int e) {
    __shared__ float4 klo[NP];
    __shared__ float4 khi[NP];
    int bh = blockIdx.x;
    int bm = bh / H_, h = bh % H_;
    int t = threadIdx.x;
    long rbase = (long)bm * NP;
    const int* idxT = g_idxT + e * UP * NP;

    const float4* gk4 = (const float4*)g_k;
    const float4* gq4 = (const float4*)g_q;
    for (int i = t; i < NP * 2; i += 256) {
        int l = i >> 1, half = i & 1;
        float4 v = gk4[(rbase + l) * 16 + h * 2 + half];
        if (half == 0) klo[l] = v; else khi[l] = v;
    }
    __syncthreads();

    for (int l = t; l < NP; l += 256) {
        long qb = (rbase + l) * 16 + h * 2;
        float4 q0 = gq4[qb], q1 = gq4[qb + 1];
        float mx = -INFINITY, sm = 0.f;
        #pragma unroll 7
        for (int u = 0; u < UP; u++) {
            int j = idxT[u * NP + l];
            float4 k0 = klo[j];
            float4 k1 = khi[j];
            float dot = q0.x*k0.x + q0.y*k0.y + q0.z*k0.z + q0.w*k0.w
                      + q1.x*k1.x + q1.y*k1.y + q1.z*k1.z + q1.w*k1.w;
            mx = fmaxf(mx, dot);
            sm += dot;
        }
        g_sp[bh * NP + l] = mx - sm / (float)NP;
    }
}

// ---------------- single-warp argmax top-35 ----------------
__global__ __launch_bounds__(32)
void argmax_kernel() {
    int bh = blockIdx.x;
    int lane = threadIdx.x;
    const float* sp = g_sp + bh * NP;
    float vals[16];
    #pragma unroll
    for (int jj = 0; jj < 16; jj++) {
        int l = lane + 32 * jj;
        vals[jj] = (l < NP) ? sp[l] : -INFINITY;
    }
    for (int it = 0; it < UP; it++) {
        float bv = -INFINITY; int bi = NP;
        #pragma unroll
        for (int jj = 0; jj < 16; jj++) {
            float v = vals[jj];
            if (v > bv) { bv = v; bi = lane + 32 * jj; }
        }
        #pragma unroll
        for (int off = 16; off; off >>= 1) {
            float ov = __shfl_xor_sync(0xffffffffu, bv, off);
            int   oi = __shfl_xor_sync(0xffffffffu, bi, off);
            if (ov > bv || (ov == bv && oi < bi)) { bv = ov; bi = oi; }
        }
        if (lane == 0) g_top[bh * UP + it] = bi;
        if ((bi & 31) == lane) {
            int tgt = bi >> 5;
            #pragma unroll
            for (int jj = 0; jj < 16; jj++)
                if (jj == tgt) vals[jj] = -INFINITY;
        }
    }
}

// ---------------- dense attention (online softmax) ----------------
__global__ __launch_bounds__(256)
void attn_dense_kernel() {
    __shared__ float4 klo[NP];
    __shared__ float4 khi[NP];
    __shared__ float4 vlo[NP];
    __shared__ float4 vhi[NP];
    __shared__ int   top[UP];
    int bm = blockIdx.x / H_, h = blockIdx.x % H_;
    int t = threadIdx.x, lane = t & 31, w = t >> 5;
    long rbase = (long)bm * NP;

    const float4* gk4 = (const float4*)g_k;
    const float4* gv4 = (const float4*)g_v;
    const float4* gq4 = (const float4*)g_q;
    for (int i = t; i < NP * 2; i += 256) {
        int l = i >> 1, half = i & 1;
        long src = (rbase + l) * 16 + h * 2 + half;
        float4 kv = gk4[src];
        float4 vv = gv4[src];
        if (half == 0) { klo[l] = kv; vlo[l] = vv; }
        else           { khi[l] = kv; vhi[l] = vv; }
    }
    if (t < UP) top[t] = g_top[blockIdx.x * UP + t];
    __syncthreads();

    float4* gc4 = (float4*)g_ctx;
    const float scale = 0.35355339059327373f;
    for (int i = w; i < UP; i += 8) {
        int l = top[i];
        long qb = (rbase + l) * 16 + h * 2;
        float4 q0 = gq4[qb], q1 = gq4[qb + 1];
        float m = -INFINITY, sum = 0.f;
        float4 a0 = make_float4(0.f, 0.f, 0.f, 0.f);
        float4 a1 = make_float4(0.f, 0.f, 0.f, 0.f);
        #pragma unroll 4
        for (int jj = 0; jj < 16; jj++) {
            int j = lane + 32 * jj;
            float s;
            if (j < NP) {
                float4 k0 = klo[j];
                float4 k1 = khi[j];
                s = (q0.x*k0.x + q0.y*k0.y + q0.z*k0.z + q0.w*k0.w
                   + q1.x*k1.x + q1.y*k1.y + q1.z*k1.z + q1.w*k1.w) * scale;
            } else s = -INFINITY;
            float mn = fmaxf(m, s);
            float corr = __expf(m - mn);
            float p    = __expf(s - mn);
            sum = sum * corr + p;
            if (j < NP) {
                float4 v0 = vlo[j];
                float4 v1 = vhi[j];
                a0.x = a0.x * corr + p * v0.x; a0.y = a0.y * corr + p * v0.y;
                a0.z = a0.z * corr + p * v0.z; a0.w = a0.w * corr + p * v0.w;
                a1.x = a1.x * corr + p * v1.x; a1.y = a1.y * corr + p * v1.y;
                a1.z = a1.z * corr + p * v1.z; a1.w = a1.w * corr + p * v1.w;
            } else {
                a0.x *= corr; a0.y *= corr; a0.z *= corr; a0.w *= corr;
                a1.x *= corr; a1.y *= corr; a1.z *= corr; a1.w *= corr;
            }
            m = mn;
        }
        float M = m;
        #pragma unroll
        for (int off = 16; off; off >>= 1)
            M = fmaxf(M, __shfl_xor_sync(0xffffffffu, M, off));
        float c = __expf(m - M);
        sum *= c;
        a0.x *= c; a0.y *= c; a0.z *= c; a0.w *= c;
        a1.x *= c; a1.y *= c; a1.z *= c; a1.w *= c;
        #pragma unroll
        for (int off = 16; off; off >>= 1) {
            sum  += __shfl_xor_sync(0xffffffffu, sum, off);
            a0.x += __shfl_xor_sync(0xffffffffu, a0.x, off);
            a0.y += __shfl_xor_sync(0xffffffffu, a0.y, off);
            a0.z += __shfl_xor_sync(0xffffffffu, a0.z, off);
            a0.w += __shfl_xor_sync(0xffffffffu, a0.w, off);
            a1.x += __shfl_xor_sync(0xffffffffu, a1.x, off);
            a1.y += __shfl_xor_sync(0xffffffffu, a1.y, off);
            a1.z += __shfl_xor_sync(0xffffffffu, a1.z, off);
            a1.w += __shfl_xor_sync(0xffffffffu, a1.w, off);
        }
        if (lane == 0) {
            float inv = 1.f / sum;
            gc4[qb]     = make_float4(a0.x*inv, a0.y*inv, a0.z*inv, a0.w*inv);
            gc4[qb + 1] = make_float4(a1.x*inv, a1.y*inv, a1.z*inv, a1.w*inv);
        }
    }
}

// ---------------- Wo GEMM + residual + LN1 ----------------
__global__ __launch_bounds__(256)
void wo_ln1_kernel(const float* __restrict__ Wo, const float* __restrict__ bo,
                   const float* __restrict__ g1, const float* __restrict__ b1) {
    extern __shared__ char smem_raw[];
    SmemG128* S = (SmemG128*)smem_raw;
    int t = threadIdx.x;
    int r0 = blockIdx.x * 128;
    int rows = NROW - r0; if (rows > 128) rows = 128;

    for (int i = t; i < 128 * 16; i += 256) {
        int row = i / 16, f4 = i % 16;
        float4 v = make_float4(0.f, 0.f, 0.f, 0.f);
        if (row < rows) v = *(const float4*)&g_ctx[(r0 + row) * DM + f4 * 4];
        *(float4*)&S->As[row][f4 * 4] = v;
    }
    {
        int c = t >> 2, ks0 = (t & 3) * 16;
        #pragma unroll
        for (int q = 0; q < 4; q++) {
            float4 wv = *(const float4*)&Wo[c * 64 + ks0 + q * 4];
            S->Bs[ks0 + q * 4 + 0][c] = wv.x;
            S->Bs[ks0 + q * 4 + 1][c] = wv.y;
            S->Bs[ks0 + q * 4 + 2][c] = wv.z;
            S->Bs[ks0 + q * 4 + 3][c] = wv.w;
        }
    }
    __syncthreads();
    int rg = t >> 4, cg = t & 15;
    float4 acc[8];
    #pragma unroll
    for (int r = 0; r < 8; r++) acc[r] = make_float4(0.f, 0.f, 0.f, 0.f);
    #pragma unroll
    for (int k = 0; k < 64; k += 4) {
        float4 b0 = *(float4*)&S->Bs[k + 0][cg * 4];
        float4 b1v = *(float4*)&S->Bs[k + 1][cg * 4];
        float4 b2 = *(float4*)&S->Bs[k + 2][cg * 4];
        float4 b3 = *(float4*)&S->Bs[k + 3][cg * 4];
        #pragma unroll
        for (int r = 0; r < 8; r++) {
            float4 a = *(float4*)&S->As[rg * 8 + r][k];
            fma4(acc[r], a.x, b0); fma4(acc[r], a.y, b1v);
            fma4(acc[r], a.z, b2); fma4(acc[r], a.w, b3);
        }
    }
    __syncthreads();
    float4 bb = *(const float4*)&bo[cg * 4];
    #pragma unroll
    for (int r = 0; r < 8; r++) {
        int row = rg * 8 + r;
        if (row < rows) {
            float4 z = *(const float4*)&g_z[(r0 + row) * DM + cg * 4];
            S->As[row][cg * 4 + 0] = acc[r].x + bb.x + z.x;
            S->As[row][cg * 4 + 1] = acc[r].y + bb.y + z.y;
            S->As[row][cg * 4 + 2] = acc[r].z + bb.z + z.z;
            S->As[row][cg * 4 + 3] = acc[r].w + bb.w + z.w;
        }
    }
    __syncthreads();
    int lane = t & 31, w2 = t >> 5;
    for (int rr = 0; rr < 16; rr++) {
        int row = w2 * 16 + rr;
        if (row >= rows) break;
        float v0 = S->As[row][lane], v1 = S->As[row][lane + 32];
        float s = v0 + v1;
        #pragma unroll
        for (int o = 16; o; o >>= 1) s += __shfl_xor_sync(0xffffffffu, s, o);
        float mu = s / 64.f;
        float d0 = v0 - mu, d1 = v1 - mu;
        float vv = d0 * d0 + d1 * d1;
        #pragma unroll
        for (int o = 16; o; o >>= 1) vv += __shfl_xor_sync(0xffffffffu, vv, o);
        float inv = rsqrtf(vv / 64.f + 1e-5f);
        g_x1[(r0 + row) * DM + lane]      = d0 * inv * g1[lane]      + b1[lane];
        g_x1[(r0 + row) * DM + lane + 32] = d1 * inv * g1[lane + 32] + b1[lane + 32];
    }
}

// ---------------- fused FFN + residual + LN2 (tf32 mma.sync) -------------
struct SmemFFN {
    float xs[64][68];
    float wb[64][68];
    float ys[64][260];
};

__global__ __launch_bounds__(256)
void ffn_ln2_kernel(const float* __restrict__ W1, const float* __restrict__ b1f,
                    const float* __restrict__ W2, const float* __restrict__ b2f,
                    const float* __restrict__ g2, const float* __restrict__ bb2) {
    extern __shared__ char smem_raw[];
    SmemFFN* S = (SmemFFN*)smem_raw;
    int t = threadIdx.x;
    int r0 = blockIdx.x * 64;
    int lane = t & 31, w = t >> 5;
    int gid = lane >> 2, tig = lane & 3;       // mma fragment coords
    int row_tile = w >> 1;                     // 0..3  -> rows row_tile*16..+16
    int col_half = w & 1;                      // 0/1   -> cols col_half*32..+32
    int rA = row_tile * 16 + gid;              // fragment rows rA, rA+8
    int cw = t >> 2, ks0 = (t & 3) * 16;       // weight-load coords

    // load x1 tile
    for (int i = t; i < 64 * 16; i += 256) {
        int row = i / 16, f4 = i % 16;
        *(float4*)&S->xs[row][f4 * 4] = *(const float4*)&g_x1[(r0 + row) * DM + f4 * 4];
    }

    // ---------- c1 (y = GELU(x @ W1^T + b1)) via tf32 mma ----------
    for (int cc = 0; cc < 4; cc++) {
        __syncthreads();
        #pragma unroll
        for (int q = 0; q < 4; q++) {
            float4 wv = *(const float4*)&W1[(cc * 64 + cw) * 64 + ks0 + q * 4];
            S->wb[ks0 + q * 4 + 0][cw] = wv.x;
            S->wb[ks0 + q * 4 + 1][cw] = wv.y;
            S->wb[ks0 + q * 4 + 2][cw] = wv.z;
            S->wb[ks0 + q * 4 + 3][cw] = wv.w;
        }
        __syncthreads();
        float acc[4][4];
        #pragma unroll
        for (int ct = 0; ct < 4; ct++)
            acc[ct][0] = acc[ct][1] = acc[ct][2] = acc[ct][3] = 0.f;
        #pragma unroll
        for (int kt = 0; kt < 8; kt++) {
            int k0 = kt * 8;
            uint32_t a0 = tf32cvt(S->xs[rA][k0 + tig]);
            uint32_t a1 = tf32cvt(S->xs[rA + 8][k0 + tig]);
            uint32_t a2 = tf32cvt(S->xs[rA][k0 + tig + 4]);
            uint32_t a3 = tf32cvt(S->xs[rA + 8][k0 + tig + 4]);
            #pragma unroll
            for (int ct = 0; ct < 4; ct++) {
                int col = col_half * 32 + ct * 8;
                uint32_t b0 = tf32cvt(S->wb[k0 + tig][col + gid]);
                uint32_t b1 = tf32cvt(S->wb[k0 + tig + 4][col + gid]);
                mma_tf32(acc[ct][0], acc[ct][1], acc[ct][2], acc[ct][3],
                         a0, a1, a2, a3, b0, b1);
            }
        }
        // bias + GELU -> ys
        #pragma unroll
        for (int ct = 0; ct < 4; ct++) {
            int colg = cc * 64 + col_half * 32 + ct * 8 + 2 * tig;
            float bia0 = b1f[colg], bia1 = b1f[colg + 1];
            float x0 = acc[ct][0] + bia0, x1 = acc[ct][1] + bia1;
            float x2 = acc[ct][2] + bia0, x3 = acc[ct][3] + bia1;
            S->ys[rA][colg]         = x0 * 0.5f * (1.f + erff(x0 * 0.7071067811865476f));
            S->ys[rA][colg + 1]     = x1 * 0.5f * (1.f + erff(x1 * 0.7071067811865476f));
            S->ys[rA + 8][colg]     = x2 * 0.5f * (1.f + erff(x2 * 0.7071067811865476f));
            S->ys[rA + 8][colg + 1] = x3 * 0.5f * (1.f + erff(x3 * 0.7071067811865476f));
        }
    }

    // ---------- c2 (out = y @ W2^T + b2) via tf32 mma ----------
    float acc2[4][4];
    #pragma unroll
    for (int ct = 0; ct < 4; ct++)
        acc2[ct][0] = acc2[ct][1] = acc2[ct][2] = acc2[ct][3] = 0.f;
    for (int kc = 0; kc < 4; kc++) {
        __syncthreads();
        #pragma unroll
        for (int q = 0; q < 4; q++) {
            float4 wv = *(const float4*)&W2[cw * 256 + kc * 64 + ks0 + q * 4];
            S->wb[ks0 + q * 4 + 0][cw] = wv.x;
            S->wb[ks0 + q * 4 + 1][cw] = wv.y;
            S->wb[ks0 + q * 4 + 2][cw] = wv.z;
            S->wb[ks0 + q * 4 + 3][cw] = wv.w;
        }
        __syncthreads();
        #pragma unroll
        for (int kt = 0; kt < 8; kt++) {
            int k0 = kt * 8;
            int kg = kc * 64 + k0;
            uint32_t a0 = tf32cvt(S->ys[rA][kg + tig]);
            uint32_t a1 = tf32cvt(S->ys[rA + 8][kg + tig]);
            uint32_t a2 = tf32cvt(S->ys[rA][kg + tig + 4]);
            uint32_t a3 = tf32cvt(S->ys[rA + 8][kg + tig + 4]);
            #pragma unroll
            for (int ct = 0; ct < 4; ct++) {
                int col = col_half * 32 + ct * 8;
                uint32_t b0 = tf32cvt(S->wb[k0 + tig][col + gid]);
                uint32_t b1 = tf32cvt(S->wb[k0 + tig + 4][col + gid]);
                mma_tf32(acc2[ct][0], acc2[ct][1], acc2[ct][2], acc2[ct][3],
                         a0, a1, a2, a3, b0, b1);
            }
        }
    }
    __syncthreads();   // wb reads done; reuse wb as output tile
    #pragma unroll
    for (int ct = 0; ct < 4; ct++) {
        int col = col_half * 32 + ct * 8 + 2 * tig;
        float bia0 = b2f[col], bia1 = b2f[col + 1];
        S->wb[rA][col]         = acc2[ct][0] + bia0 + S->xs[rA][col];
        S->wb[rA][col + 1]     = acc2[ct][1] + bia1 + S->xs[rA][col + 1];
        S->wb[rA + 8][col]     = acc2[ct][2] + bia0 + S->xs[rA + 8][col];
        S->wb[rA + 8][col + 1] = acc2[ct][3] + bia1 + S->xs[rA + 8][col + 1];
    }
    __syncthreads();
    // LN2 over wb rows -> g_z
    #pragma unroll
    for (int rr = 0; rr < 8; rr++) {
        int row = w * 8 + rr;
        float v0 = S->wb[row][lane], v1 = S->wb[row][lane + 32];
        float s = v0 + v1;
        #pragma unroll
        for (int o = 16; o; o >>= 1) s += __shfl_xor_sync(0xffffffffu, s, o);
        float mu = s / 64.f;
        float d0 = v0 - mu, d1 = v1 - mu;
        float vv = d0 * d0 + d1 * d1;
        #pragma unroll
        for (int o = 16; o; o >>= 1) vv += __shfl_xor_sync(0xffffffffu, vv, o);
        float inv = rsqrtf(vv / 64.f + 1e-5f);
        g_z[(r0 + row) * DM + lane]      = d0 * inv * g2[lane]      + bb2[lane];
        g_z[(r0 + row) * DM + lane + 32] = d1 * inv * g2[lane + 32] + bb2[lane + 32];
    }
}

// ---------------- final LN ----------------
__global__ void final_ln_kernel(const float* __restrict__ gf, const float* __restrict__ bf) {
    int t = threadIdx.x, lane = t & 31, w = t >> 5;
    int r = blockIdx.x * 8 + w;
    float v0 = g_z[r * DM + lane], v1 = g_z[r * DM + lane + 32];
    float s = v0 + v1;
    #pragma unroll
    for (int o = 16; o; o >>= 1) s += __shfl_xor_sync(0xffffffffu, s, o);
    float mu = s / 64.f;
    float d0 = v0 - mu, d1 = v1 - mu;
    float vv = d0 * d0 + d1 * d1;
    #pragma unroll
    for (int o = 16; o; o >>= 1) vv += __shfl_xor_sync(0xffffffffu, vv, o);
    float inv = rsqrtf(vv / 64.f + 1e-5f);
    g_z[r * DM + lane]      = d0 * inv * gf[lane]      + bf[lane];
    g_z[r * DM + lane + 32] = d1 * inv * gf[lane + 32] + bf[lane + 32];
}

// ---------------- output projection ----------------
__global__ void proj_partial_kernel(const float* __restrict__ outW) {
    int seg = blockIdx.x;
    int bg  = blockIdx.y;
    __shared__ float zc[8][SEG];
    int t = threadIdx.x, lane = t & 31, w = t >> 5;
    int k0 = seg * SEG;
    for (int i = t; i < 8 * SEG; i += 256) {
        int bmo = i / SEG, kk = i % SEG;
        zc[bmo][kk] = g_z[(bg * 8 + bmo) * KTOT + k0 + kk];
    }
    __syncthreads();
    for (int p = w; p < PRED; p += 8) {
        float acc[8] = {0.f, 0.f, 0.f, 0.f, 0.f, 0.f, 0.f, 0.f};
        for (int kk = lane; kk < SEG; kk += 32) {
            float ww = outW[p * KTOT + k0 + kk];
            #pragma unroll
            for (int bmo = 0; bmo < 8; bmo++) acc[bmo] += ww * zc[bmo][kk];
        }
        #pragma unroll
        for (int bmo = 0; bmo < 8; bmo++) {
            #pragma unroll
            for (int o = 16; o; o >>= 1)
                acc[bmo] += __shfl_xor_sync(0xffffffffu, acc[bmo], o);
        }
        if (lane == 0) {
            #pragma unroll
            for (int bmo = 0; bmo < 8; bmo++)
                g_pp[(p * BM + bg * 8 + bmo) * NSEG + seg] = acc[bmo];
        }
    }
}

__global__ void proj_reduce_kernel(const float* __restrict__ outb, float* __restrict__ out) {
    int i = blockIdx.x * 256 + threadIdx.x;
    if (i >= PRED * BM) return;
    int p = i / BM, bm = i % BM;
    float s = outb[p];
    #pragma unroll
    for (int seg = 0; seg < NSEG; seg++) s += g_pp[(p * BM + bm) * NSEG + seg];
    int b = bm / M_, m = bm % M_;
    out[(b * PRED + p) * M_ + m] = s;
}

// ---------------- launch ----------------
extern "C" void kernel_launch(void* const* d_in, const int* in_sizes, int n_in,
                              void* d_out, int out_size) {
    const float* x_enc = (const float*)d_in[0];
    const float* in_W  = (const float*)d_in[4];
    const float* in_b  = (const float*)d_in[5];
    const float* Wq    = (const float*)d_in[6];
    const float* bq    = (const float*)d_in[7];
    const float* Wk    = (const float*)d_in[8];
    const float* bk    = (const float*)d_in[9];
    const float* Wv    = (const float*)d_in[10];
    const float* bv    = (const float*)d_in[11];
    const float* Wo    = (const float*)d_in[12];
    const float* bo    = (const float*)d_in[13];
    const float* c1_W  = (const float*)d_in[14];
    const float* c1_b  = (const float*)d_in[15];
    const float* c2_W  = (const float*)d_in[16];
    const float* c2_b  = (const float*)d_in[17];
    const float* ln1_g = (const float*)d_in[18];
    const float* ln1_b = (const float*)d_in[19];
    const float* ln2_g = (const float*)d_in[20];
    const float* ln2_b = (const float*)d_in[21];
    const float* lnf_g = (const float*)d_in[22];
    const float* lnf_b = (const float*)d_in[23];
    const float* out_W = (const float*)d_in[24];
    const float* out_b = (const float*)d_in[25];
    float* out = (float*)d_out;

    const int smemG = sizeof(SmemG128);
    const int smemF = sizeof(SmemFFN);
    cudaFuncSetAttribute(qkv_kernel,    cudaFuncAttributeMaxDynamicSharedMemorySize, smemG);
    cudaFuncSetAttribute(wo_ln1_kernel, cudaFuncAttributeMaxDynamicSharedMemorySize, smemG);
    cudaFuncSetAttribute(ffn_ln2_kernel,cudaFuncAttributeMaxDynamicSharedMemorySize, smemF);

    static cudaStream_t s2 = nullptr;
    static cudaEvent_t evFork = nullptr, evIdx = nullptr;
    static cudaEvent_t evQ[2] = {nullptr, nullptr}, evV[2] = {nullptr, nullptr};
    if (s2 == nullptr) {
        cudaStreamCreateWithFlags(&s2, cudaStreamNonBlocking);
        cudaEventCreateWithFlags(&evFork, cudaEventDisableTiming);
        cudaEventCreateWithFlags(&evIdx,  cudaEventDisableTiming);
        for (int e = 0; e < 2; e++) {
            cudaEventCreateWithFlags(&evQ[e], cudaEventDisableTiming);
            cudaEventCreateWithFlags(&evV[e], cudaEventDisableTiming);
        }
    }

    cudaEventRecord(evFork, 0);
    cudaStreamWaitEvent(s2, evFork, 0);

    rand_idx_kernel<<<(2 * NP * UP + 255) / 256, 256, 0, s2>>>();
    cudaEventRecord(evIdx, s2);

    patch_embed_kernel<<<NROW / 16, 256>>>(x_enc, in_W, in_b);
    cudaStreamWaitEvent(0, evIdx, 0);

    for (int e = 0; e < 2; e++) {
        qkv_kernel<<<dim3(256, 3), 256, smemG>>>(Wq + e * DM * DM, bq + e * DM,
                                                 Wk + e * DM * DM, bk + e * DM,
                                                 Wv + e * DM * DM, bv + e * DM);
        cudaEventRecord(evQ[e], 0);

        cudaStreamWaitEvent(s2, evQ[e], 0);
        vmean_kernel<<<BM, 256, 0, s2>>>();
        bcast_kernel<<<NROW * 16 / 256, 256, 0, s2>>>();
        cudaEventRecord(evV[e], s2);

        sparsity_kernel<<<BM * H_, 256>>>(e);
        argmax_kernel<<<BM * H_, 32>>>();

        cudaStreamWaitEvent(0, evV[e], 0);
        attn_dense_kernel<<<BM * H_, 256>>>();
        wo_ln1_kernel<<<256, 256, smemG>>>(Wo + e * DM * DM, bo + e * DM,
                                           ln1_g + e * DM, ln1_b + e * DM);
        ffn_ln2_kernel<<<NROW / 64, 256, smemF>>>(c1_W + e * DFF * DM, c1_b + e * DFF,
                                                  c2_W + e * DM * DFF, c2_b + e * DM,
                                                  ln2_g + e * DM, ln2_b + e * DM);
    }

    final_ln_kernel<<<NROW / 8, 256>>>(lnf_g, lnf_b);
    proj_partial_kernel<<<dim3(NSEG, 8), 256>>>(out_W);
    proj_reduce_kernel<<<(PRED * BM + 255) / 256, 256>>>(out_b, out);
}

// round 16
// speedup vs baseline: 1.2848x; 1.0311x over previous
#include <cuda_runtime.h>
#include <cstdint>
#include <math.h>

#define B_      8
#define M_      8
#define BM      64
#define SL      4096
#define P_      16
#define STRIDE_ 8
#define NP      511
#define DM      64
#define H_      8
#define DH      8
#define DFF     256
#define PRED    96
#define UP      35
#define NROW    (BM*NP)      // 32704
#define KTOT    (NP*DM)      // 32704
#define NSEG    32
#define SEG     1022

// ---------------- scratch ----------------
__device__ float g_z  [NROW*DM];
__device__ float g_q  [NROW*DM];
__device__ float g_k  [NROW*DM];
__device__ float g_v  [NROW*DM];
__device__ float g_ctx[NROW*DM];
__device__ float g_x1 [NROW*DM];
__device__ int   g_idxT[2*UP*NP];        // [e][u][l]
__device__ float g_sp [BM*H_*NP];
__device__ int   g_top[BM*H_*UP];
__device__ float g_vmean[BM*DM];
__device__ float g_pp [PRED*BM*NSEG];

__device__ __forceinline__ void fma4(float4& o, float s, const float4& b) {
    o.x += s * b.x; o.y += s * b.y; o.z += s * b.z; o.w += s * b.w;
}

// ---------------- tf32 mma helpers ----------------
__device__ __forceinline__ uint32_t tf32cvt(float v) {
    uint32_t r;
    asm("cvt.rna.tf32.f32 %0, %1;" : "=r"(r) : "f"(v));
    return r;
}

__device__ __forceinline__ void mma_tf32(float& c0, float& c1, float& c2, float& c3,
                                         uint32_t a0, uint32_t a1, uint32_t a2, uint32_t a3,
                                         uint32_t b0, uint32_t b1) {
    asm volatile(
        "mma.sync.aligned.m16n8k8.row.col.f32.tf32.tf32.f32 "
        "{%0,%1,%2,%3},{%4,%5,%6,%7},{%8,%9},{%0,%1,%2,%3};"
        : "+f"(c0), "+f"(c1), "+f"(c2), "+f"(c3)
        : "r"(a0), "r"(a1), "r"(a2), "r"(a3), "r"(b0), "r"(b1));
}

// ---------------- threefry2x32 (bitwise JAX-compatible) ----------------
__device__ __forceinline__ uint32_t rotl32(uint32_t v, int r) {
    return (v << r) | (v >> (32 - r));
}

__device__ __forceinline__ void tf2x32(uint32_t k0, uint32_t k1,
                                       uint32_t& x0, uint32_t& x1) {
    uint32_t ks0 = k0, ks1 = k1, ks2 = k0 ^ k1 ^ 0x1BD11BDAu;
    const int ra[4] = {13, 15, 26, 6};
    const int rb[4] = {17, 29, 16, 24};
    x0 += ks0; x1 += ks1;
    #pragma unroll
    for (int i = 0; i < 4; i++) { x0 += x1; x1 = rotl32(x1, ra[i]); x1 ^= x0; }
    x0 += ks1; x1 += ks2 + 1u;
    #pragma unroll
    for (int i = 0; i < 4; i++) { x0 += x1; x1 = rotl32(x1, rb[i]); x1 ^= x0; }
    x0 += ks2; x1 += ks0 + 2u;
    #pragma unroll
    for (int i = 0; i < 4; i++) { x0 += x1; x1 = rotl32(x1, ra[i]); x1 ^= x0; }
    x0 += ks0; x1 += ks1 + 3u;
    #pragma unroll
    for (int i = 0; i < 4; i++) { x0 += x1; x1 = rotl32(x1, rb[i]); x1 ^= x0; }
    x0 += ks1; x1 += ks2 + 4u;
    #pragma unroll
    for (int i = 0; i < 4; i++) { x0 += x1; x1 = rotl32(x1, ra[i]); x1 ^= x0; }
    x0 += ks2; x1 += ks0 + 5u;
}

__device__ __forceinline__ uint32_t rbits17885(uint32_t k0, uint32_t k1, int j) {
    const int HALF = 8943;
    uint32_t x0, x1;
    if (j < HALF) {
        x0 = (uint32_t)j;
        x1 = (j < HALF - 1) ? (uint32_t)(j + HALF) : 0u;
        tf2x32(k0, k1, x0, x1);
        return x0;
    } else {
        x0 = (uint32_t)(j - HALF);
        x1 = (uint32_t)j;
        tf2x32(k0, k1, x0, x1);
        return x1;
    }
}

__global__ void rand_idx_kernel() {
    int j2 = blockIdx.x * blockDim.x + threadIdx.x;
    if (j2 >= 2 * NP * UP) return;
    int e = j2 / (NP * UP);
    int j = j2 % (NP * UP);
    uint32_t f0 = 0u, f1 = (uint32_t)e;
    tf2x32(0u, 1u, f0, f1);
    uint32_t a0 = 0u, a1 = 2u; tf2x32(f0, f1, a0, a1);
    uint32_t b0 = 1u, b1 = 3u; tf2x32(f0, f1, b0, b1);
    uint32_t hi = rbits17885(a0, b0, j);
    uint32_t lo = rbits17885(a1, b1, j);
    uint32_t off = ((hi % 511u) * 32u + (lo % 511u)) % 511u;
    int l = j / UP, u = j % UP;
    g_idxT[e * UP * NP + u * NP + l] = (int)off;
}

// ---------------- patch embedding ----------------
__global__ void patch_embed_kernel(const float* __restrict__ xe,
                                   const float* __restrict__ inW,
                                   const float* __restrict__ inb) {
    __shared__ float ps[16][17];
    __shared__ float ws[64][17];
    __shared__ float bs[64];
    int t = threadIdx.x;
    int r0 = blockIdx.x * 16;
    {
        int rr = t / 16, p = t % 16;
        int r = r0 + rr;
        int bm = r / NP, n = r % NP;
        int b = bm / M_, m = bm % M_;
        ps[rr][p] = xe[(b * SL + n * STRIDE_ + p) * M_ + m];
    }
    for (int i = t; i < 64 * P_; i += 256) ws[i / P_][i % P_] = inW[i];
    if (t < 64) bs[t] = inb[t];
    __syncthreads();
    int c = t % 64, q4 = t / 64;
    #pragma unroll
    for (int rr = q4 * 4; rr < q4 * 4 + 4; rr++) {
        float acc = bs[c];
        #pragma unroll
        for (int p = 0; p < P_; p++) acc += ws[c][p] * ps[rr][p];
        g_z[(r0 + rr) * DM + c] = acc;
    }
}

// ---------------- QKV GEMM (tf32 mma) ----------------
struct SmemG128 {
    float As[128][68];
    float Bs[64][68];
};

__global__ __launch_bounds__(256)
void qkv_kernel(const float* __restrict__ Wq, const float* __restrict__ bq,
                const float* __restrict__ Wk, const float* __restrict__ bk,
                const float* __restrict__ Wv, const float* __restrict__ bv) {
    extern __shared__ char smem_raw[];
    SmemG128* S = (SmemG128*)smem_raw;
    int t = threadIdx.x;
    int r0 = blockIdx.x * 128;
    int rows = NROW - r0; if (rows > 128) rows = 128;
    const float* W; const float* bias; float* out;
    if (blockIdx.y == 0)      { W = Wq; bias = bq; out = g_q; }
    else if (blockIdx.y == 1) { W = Wk; bias = bk; out = g_k; }
    else                      { W = Wv; bias = bv; out = g_v; }

    for (int i = t; i < 128 * 16; i += 256) {
        int row = i / 16, f4 = i % 16;
        float4 v = make_float4(0.f, 0.f, 0.f, 0.f);
        if (row < rows) v = *(const float4*)&g_z[(r0 + row) * DM + f4 * 4];
        *(float4*)&S->As[row][f4 * 4] = v;
    }
    {
        int c = t >> 2, ks0 = (t & 3) * 16;
        #pragma unroll
        for (int q = 0; q < 4; q++) {
            float4 wv = *(const float4*)&W[c * 64 + ks0 + q * 4];
            S->Bs[ks0 + q * 4 + 0][c] = wv.x;
            S->Bs[ks0 + q * 4 + 1][c] = wv.y;
            S->Bs[ks0 + q * 4 + 2][c] = wv.z;
            S->Bs[ks0 + q * 4 + 3][c] = wv.w;
        }
    }
    __syncthreads();

    int lane = t & 31, w = t >> 5;
    int gid = lane >> 2, tig = lane & 3;
    int rA = w * 16 + gid;                 // warp owns rows w*16..w*16+15

    float acc[8][4];
    #pragma unroll
    for (int ct = 0; ct < 8; ct++)
        acc[ct][0] = acc[ct][1] = acc[ct][2] = acc[ct][3] = 0.f;

    #pragma unroll
    for (int kt = 0; kt < 8; kt++) {
        int k0 = kt * 8;
        uint32_t a0 = tf32cvt(S->As[rA][k0 + tig]);
        uint32_t a1 = tf32cvt(S->As[rA + 8][k0 + tig]);
        uint32_t a2 = tf32cvt(S->As[rA][k0 + tig + 4]);
        uint32_t a3 = tf32cvt(S->As[rA + 8][k0 + tig + 4]);
        #pragma unroll
        for (int ct = 0; ct < 8; ct++) {
            int col = ct * 8;
            uint32_t b0 = tf32cvt(S->Bs[k0 + tig][col + gid]);
            uint32_t b1 = tf32cvt(S->Bs[k0 + tig + 4][col + gid]);
            mma_tf32(acc[ct][0], acc[ct][1], acc[ct][2], acc[ct][3],
                     a0, a1, a2, a3, b0, b1);
        }
    }

    #pragma unroll
    for (int ct = 0; ct < 8; ct++) {
        int col = ct * 8 + 2 * tig;
        float bia0 = bias[col], bia1 = bias[col + 1];
        if (rA < rows)
            *(float2*)&out[(r0 + rA) * DM + col] =
                make_float2(acc[ct][0] + bia0, acc[ct][1] + bia1);
        if (rA + 8 < rows)
            *(float2*)&out[(r0 + rA + 8) * DM + col] =
                make_float2(acc[ct][2] + bia0, acc[ct][3] + bia1);
    }
}

// ---------------- V mean per bm ----------------
__global__ __launch_bounds__(256)
void vmean_kernel() {
    __shared__ float part[4][64];
    int bm = blockIdx.x;
    int t = threadIdx.x;
    int col = t & 63, slice = t >> 6;
    float s = 0.f;
    for (int l = slice; l < NP; l += 4) s += g_v[(bm * NP + l) * DM + col];
    part[slice][col] = s;
    __syncthreads();
    if (t < 64) {
        float v = (part[0][t] + part[1][t] + part[2][t] + part[3][t]) / (float)NP;
        g_vmean[bm * DM + t] = v;
    }
}

// ---------------- broadcast vmean into g_ctx ----------------
__global__ __launch_bounds__(256)
void bcast_kernel() {
    int i = blockIdx.x * 256 + threadIdx.x;
    int row = i >> 4, f4 = i & 15;
    int bm = row / NP;
    ((float4*)g_ctx)[i] = ((const float4*)g_vmean)[bm * 16 + f4];
}

// ---------------- sparsity scores ----------------
__global__ __launch_bounds__(256)
void sparsity_kernel(int e) {
    __shared__ float4 klo[NP];
    __shared__ float4 khi[NP];
    int bh = blockIdx.x;
    int bm = bh / H_, h = bh % H_;
    int t = threadIdx.x;
    long rbase = (long)bm * NP;
    const int* idxT = g_idxT + e * UP * NP;

    const float4* gk4 = (const float4*)g_k;
    const float4* gq4 = (const float4*)g_q;
    for (int i = t; i < NP * 2; i += 256) {
        int l = i >> 1, half = i & 1;
        float4 v = gk4[(rbase + l) * 16 + h * 2 + half];
        if (half == 0) klo[l] = v; else khi[l] = v;
    }
    __syncthreads();

    for (int l = t; l < NP; l += 256) {
        long qb = (rbase + l) * 16 + h * 2;
        float4 q0 = gq4[qb], q1 = gq4[qb + 1];
        float mx = -INFINITY, sm = 0.f;
        #pragma unroll 7
        for (int u = 0; u < UP; u++) {
            int j = idxT[u * NP + l];
            float4 k0 = klo[j];
            float4 k1 = khi[j];
            float dot = q0.x*k0.x + q0.y*k0.y + q0.z*k0.z + q0.w*k0.w
                      + q1.x*k1.x + q1.y*k1.y + q1.z*k1.z + q1.w*k1.w;
            mx = fmaxf(mx, dot);
            sm += dot;
        }
        g_sp[bh * NP + l] = mx - sm / (float)NP;
    }
}

// ---------------- single-warp argmax top-35 ----------------
__global__ __launch_bounds__(32)
void argmax_kernel() {
    int bh = blockIdx.x;
    int lane = threadIdx.x;
    const float* sp = g_sp + bh * NP;
    float vals[16];
    #pragma unroll
    for (int jj = 0; jj < 16; jj++) {
        int l = lane + 32 * jj;
        vals[jj] = (l < NP) ? sp[l] : -INFINITY;
    }
    for (int it = 0; it < UP; it++) {
        float bv = -INFINITY; int bi = NP;
        #pragma unroll
        for (int jj = 0; jj < 16; jj++) {
            float v = vals[jj];
            if (v > bv) { bv = v; bi = lane + 32 * jj; }
        }
        #pragma unroll
        for (int off = 16; off; off >>= 1) {
            float ov = __shfl_xor_sync(0xffffffffu, bv, off);
            int   oi = __shfl_xor_sync(0xffffffffu, bi, off);
            if (ov > bv || (ov == bv && oi < bi)) { bv = ov; bi = oi; }
        }
        if (lane == 0) g_top[bh * UP + it] = bi;
        if ((bi & 31) == lane) {
            int tgt = bi >> 5;
            #pragma unroll
            for (int jj = 0; jj < 16; jj++)
                if (jj == tgt) vals[jj] = -INFINITY;
        }
    }
}

// ---------------- dense attention (online softmax) ----------------
__global__ __launch_bounds__(256)
void attn_dense_kernel() {
    __shared__ float4 klo[NP];
    __shared__ float4 khi[NP];
    __shared__ float4 vlo[NP];
    __shared__ float4 vhi[NP];
    __shared__ int   top[UP];
    int bm = blockIdx.x / H_, h = blockIdx.x % H_;
    int t = threadIdx.x, lane = t & 31, w = t >> 5;
    long rbase = (long)bm * NP;

    const float4* gk4 = (const float4*)g_k;
    const float4* gv4 = (const float4*)g_v;
    const float4* gq4 = (const float4*)g_q;
    for (int i = t; i < NP * 2; i += 256) {
        int l = i >> 1, half = i & 1;
        long src = (rbase + l) * 16 + h * 2 + half;
        float4 kv = gk4[src];
        float4 vv = gv4[src];
        if (half == 0) { klo[l] = kv; vlo[l] = vv; }
        else           { khi[l] = kv; vhi[l] = vv; }
    }
    if (t < UP) top[t] = g_top[blockIdx.x * UP + t];
    __syncthreads();

    float4* gc4 = (float4*)g_ctx;
    const float scale = 0.35355339059327373f;
    for (int i = w; i < UP; i += 8) {
        int l = top[i];
        long qb = (rbase + l) * 16 + h * 2;
        float4 q0 = gq4[qb], q1 = gq4[qb + 1];
        float m = -INFINITY, sum = 0.f;
        float4 a0 = make_float4(0.f, 0.f, 0.f, 0.f);
        float4 a1 = make_float4(0.f, 0.f, 0.f, 0.f);
        #pragma unroll 4
        for (int jj = 0; jj < 16; jj++) {
            int j = lane + 32 * jj;
            float s;
            if (j < NP) {
                float4 k0 = klo[j];
                float4 k1 = khi[j];
                s = (q0.x*k0.x + q0.y*k0.y + q0.z*k0.z + q0.w*k0.w
                   + q1.x*k1.x + q1.y*k1.y + q1.z*k1.z + q1.w*k1.w) * scale;
            } else s = -INFINITY;
            float mn = fmaxf(m, s);
            float corr = __expf(m - mn);
            float p    = __expf(s - mn);
            sum = sum * corr + p;
            if (j < NP) {
                float4 v0 = vlo[j];
                float4 v1 = vhi[j];
                a0.x = a0.x * corr + p * v0.x; a0.y = a0.y * corr + p * v0.y;
                a0.z = a0.z * corr + p * v0.z; a0.w = a0.w * corr + p * v0.w;
                a1.x = a1.x * corr + p * v1.x; a1.y = a1.y * corr + p * v1.y;
                a1.z = a1.z * corr + p * v1.z; a1.w = a1.w * corr + p * v1.w;
            } else {
                a0.x *= corr; a0.y *= corr; a0.z *= corr; a0.w *= corr;
                a1.x *= corr; a1.y *= corr; a1.z *= corr; a1.w *= corr;
            }
            m = mn;
        }
        float M = m;
        #pragma unroll
        for (int off = 16; off; off >>= 1)
            M = fmaxf(M, __shfl_xor_sync(0xffffffffu, M, off));
        float c = __expf(m - M);
        sum *= c;
        a0.x *= c; a0.y *= c; a0.z *= c; a0.w *= c;
        a1.x *= c; a1.y *= c; a1.z *= c; a1.w *= c;
        #pragma unroll
        for (int off = 16; off; off >>= 1) {
            sum  += __shfl_xor_sync(0xffffffffu, sum, off);
            a0.x += __shfl_xor_sync(0xffffffffu, a0.x, off);
            a0.y += __shfl_xor_sync(0xffffffffu, a0.y, off);
            a0.z += __shfl_xor_sync(0xffffffffu, a0.z, off);
            a0.w += __shfl_xor_sync(0xffffffffu, a0.w, off);
            a1.x += __shfl_xor_sync(0xffffffffu, a1.x, off);
            a1.y += __shfl_xor_sync(0xffffffffu, a1.y, off);
            a1.z += __shfl_xor_sync(0xffffffffu, a1.z, off);
            a1.w += __shfl_xor_sync(0xffffffffu, a1.w, off);
        }
        if (lane == 0) {
            float inv = 1.f / sum;
            gc4[qb]     = make_float4(a0.x*inv, a0.y*inv, a0.z*inv, a0.w*inv);
            gc4[qb + 1] = make_float4(a1.x*inv, a1.y*inv, a1.z*inv, a1.w*inv);
        }
    }
}

// ---------------- Wo GEMM + residual + LN1 (tf32 mma) ----------------
__global__ __launch_bounds__(256)
void wo_ln1_kernel(const float* __restrict__ Wo, const float* __restrict__ bo,
                   const float* __restrict__ g1, const float* __restrict__ b1) {
    extern __shared__ char smem_raw[];
    SmemG128* S = (SmemG128*)smem_raw;
    int t = threadIdx.x;
    int r0 = blockIdx.x * 128;
    int rows = NROW - r0; if (rows > 128) rows = 128;

    for (int i = t; i < 128 * 16; i += 256) {
        int row = i / 16, f4 = i % 16;
        float4 v = make_float4(0.f, 0.f, 0.f, 0.f);
        if (row < rows) v = *(const float4*)&g_ctx[(r0 + row) * DM + f4 * 4];
        *(float4*)&S->As[row][f4 * 4] = v;
    }
    {
        int c = t >> 2, ks0 = (t & 3) * 16;
        #pragma unroll
        for (int q = 0; q < 4; q++) {
            float4 wv = *(const float4*)&Wo[c * 64 + ks0 + q * 4];
            S->Bs[ks0 + q * 4 + 0][c] = wv.x;
            S->Bs[ks0 + q * 4 + 1][c] = wv.y;
            S->Bs[ks0 + q * 4 + 2][c] = wv.z;
            S->Bs[ks0 + q * 4 + 3][c] = wv.w;
        }
    }
    __syncthreads();

    int lane = t & 31, w = t >> 5;
    int gid = lane >> 2, tig = lane & 3;
    int rA = w * 16 + gid;

    float acc[8][4];
    #pragma unroll
    for (int ct = 0; ct < 8; ct++)
        acc[ct][0] = acc[ct][1] = acc[ct][2] = acc[ct][3] = 0.f;

    #pragma unroll
    for (int kt = 0; kt < 8; kt++) {
        int k0 = kt * 8;
        uint32_t a0 = tf32cvt(S->As[rA][k0 + tig]);
        uint32_t a1 = tf32cvt(S->As[rA + 8][k0 + tig]);
        uint32_t a2 = tf32cvt(S->As[rA][k0 + tig + 4]);
        uint32_t a3 = tf32cvt(S->As[rA + 8][k0 + tig + 4]);
        #pragma unroll
        for (int ct = 0; ct < 8; ct++) {
            int col = ct * 8;
            uint32_t b0 = tf32cvt(S->Bs[k0 + tig][col + gid]);
            uint32_t b1 = tf32cvt(S->Bs[k0 + tig + 4][col + gid]);
            mma_tf32(acc[ct][0], acc[ct][1], acc[ct][2], acc[ct][3],
                     a0, a1, a2, a3, b0, b1);
        }
    }

    // epilogue: bias + residual into As (warp-private rows), then LN
    __syncthreads();
    #pragma unroll
    for (int ct = 0; ct < 8; ct++) {
        int col = ct * 8 + 2 * tig;
        float bia0 = bo[col], bia1 = bo[col + 1];
        if (rA < rows) {
            float2 z = *(const float2*)&g_z[(r0 + rA) * DM + col];
            S->As[rA][col]     = acc[ct][0] + bia0 + z.x;
            S->As[rA][col + 1] = acc[ct][1] + bia1 + z.y;
        }
        if (rA + 8 < rows) {
            float2 z = *(const float2*)&g_z[(r0 + rA + 8) * DM + col];
            S->As[rA + 8][col]     = acc[ct][2] + bia0 + z.x;
            S->As[rA + 8][col + 1] = acc[ct][3] + bia1 + z.y;
        }
    }
    __syncthreads();
    for (int rr = 0; rr < 16; rr++) {
        int row = w * 16 + rr;
        if (row >= rows) break;
        float v0 = S->As[row][lane], v1 = S->As[row][lane + 32];
        float s = v0 + v1;
        #pragma unroll
        for (int o = 16; o; o >>= 1) s += __shfl_xor_sync(0xffffffffu, s, o);
        float mu = s / 64.f;
        float d0 = v0 - mu, d1 = v1 - mu;
        float vv = d0 * d0 + d1 * d1;
        #pragma unroll
        for (int o = 16; o; o >>= 1) vv += __shfl_xor_sync(0xffffffffu, vv, o);
        float inv = rsqrtf(vv / 64.f + 1e-5f);
        g_x1[(r0 + row) * DM + lane]      = d0 * inv * g1[lane]      + b1[lane];
        g_x1[(r0 + row) * DM + lane + 32] = d1 * inv * g1[lane + 32] + b1[lane + 32];
    }
}

// ---------------- fused FFN + residual + LN2 (tf32 mma.sync) -------------
struct SmemFFN {
    float xs[64][68];
    float wb[64][68];
    float ys[64][260];
};

__global__ __launch_bounds__(256)
void ffn_ln2_kernel(const float* __restrict__ W1, const float* __restrict__ b1f,
                    const float* __restrict__ W2, const float* __restrict__ b2f,
                    const float* __restrict__ g2, const float* __restrict__ bb2) {
    extern __shared__ char smem_raw[];
    SmemFFN* S = (SmemFFN*)smem_raw;
    int t = threadIdx.x;
    int r0 = blockIdx.x * 64;
    int lane = t & 31, w = t >> 5;
    int gid = lane >> 2, tig = lane & 3;
    int row_tile = w >> 1;
    int col_half = w & 1;
    int rA = row_tile * 16 + gid;
    int cw = t >> 2, ks0 = (t & 3) * 16;

    for (int i = t; i < 64 * 16; i += 256) {
        int row = i / 16, f4 = i % 16;
        *(float4*)&S->xs[row][f4 * 4] = *(const float4*)&g_x1[(r0 + row) * DM + f4 * 4];
    }

    for (int cc = 0; cc < 4; cc++) {
        __syncthreads();
        #pragma unroll
        for (int q = 0; q < 4; q++) {
            float4 wv = *(const float4*)&W1[(cc * 64 + cw) * 64 + ks0 + q * 4];
            S->wb[ks0 + q * 4 + 0][cw] = wv.x;
            S->wb[ks0 + q * 4 + 1][cw] = wv.y;
            S->wb[ks0 + q * 4 + 2][cw] = wv.z;
            S->wb[ks0 + q * 4 + 3][cw] = wv.w;
        }
        __syncthreads();
        float acc[4][4];
        #pragma unroll
        for (int ct = 0; ct < 4; ct++)
            acc[ct][0] = acc[ct][1] = acc[ct][2] = acc[ct][3] = 0.f;
        #pragma unroll
        for (int kt = 0; kt < 8; kt++) {
            int k0 = kt * 8;
            uint32_t a0 = tf32cvt(S->xs[rA][k0 + tig]);
            uint32_t a1 = tf32cvt(S->xs[rA + 8][k0 + tig]);
            uint32_t a2 = tf32cvt(S->xs[rA][k0 + tig + 4]);
            uint32_t a3 = tf32cvt(S->xs[rA + 8][k0 + tig + 4]);
            #pragma unroll
            for (int ct = 0; ct < 4; ct++) {
                int col = col_half * 32 + ct * 8;
                uint32_t b0 = tf32cvt(S->wb[k0 + tig][col + gid]);
                uint32_t b1 = tf32cvt(S->wb[k0 + tig + 4][col + gid]);
                mma_tf32(acc[ct][0], acc[ct][1], acc[ct][2], acc[ct][3],
                         a0, a1, a2, a3, b0, b1);
            }
        }
        #pragma unroll
        for (int ct = 0; ct < 4; ct++) {
            int colg = cc * 64 + col_half * 32 + ct * 8 + 2 * tig;
            float bia0 = b1f[colg], bia1 = b1f[colg + 1];
            float x0 = acc[ct][0] + bia0, x1 = acc[ct][1] + bia1;
            float x2 = acc[ct][2] + bia0, x3 = acc[ct][3] + bia1;
            S->ys[rA][colg]         = x0 * 0.5f * (1.f + erff(x0 * 0.7071067811865476f));
            S->ys[rA][colg + 1]     = x1 * 0.5f * (1.f + erff(x1 * 0.7071067811865476f));
            S->ys[rA + 8][colg]     = x2 * 0.5f * (1.f + erff(x2 * 0.7071067811865476f));
            S->ys[rA + 8][colg + 1] = x3 * 0.5f * (1.f + erff(x3 * 0.7071067811865476f));
        }
    }

    float acc2[4][4];
    #pragma unroll
    for (int ct = 0; ct < 4; ct++)
        acc2[ct][0] = acc2[ct][1] = acc2[ct][2] = acc2[ct][3] = 0.f;
    for (int kc = 0; kc < 4; kc++) {
        __syncthreads();
        #pragma unroll
        for (int q = 0; q < 4; q++) {
            float4 wv = *(const float4*)&W2[cw * 256 + kc * 64 + ks0 + q * 4];
            S->wb[ks0 + q * 4 + 0][cw] = wv.x;
            S->wb[ks0 + q * 4 + 1][cw] = wv.y;
            S->wb[ks0 + q * 4 + 2][cw] = wv.z;
            S->wb[ks0 + q * 4 + 3][cw] = wv.w;
        }
        __syncthreads();
        #pragma unroll
        for (int kt = 0; kt < 8; kt++) {
            int k0 = kt * 8;
            int kg = kc * 64 + k0;
            uint32_t a0 = tf32cvt(S->ys[rA][kg + tig]);
            uint32_t a1 = tf32cvt(S->ys[rA + 8][kg + tig]);
            uint32_t a2 = tf32cvt(S->ys[rA][kg + tig + 4]);
            uint32_t a3 = tf32cvt(S->ys[rA + 8][kg + tig + 4]);
            #pragma unroll
            for (int ct = 0; ct < 4; ct++) {
                int col = col_half * 32 + ct * 8;
                uint32_t b0 = tf32cvt(S->wb[k0 + tig][col + gid]);
                uint32_t b1 = tf32cvt(S->wb[k0 + tig + 4][col + gid]);
                mma_tf32(acc2[ct][0], acc2[ct][1], acc2[ct][2], acc2[ct][3],
                         a0, a1, a2, a3, b0, b1);
            }
        }
    }
    __syncthreads();
    #pragma unroll
    for (int ct = 0; ct < 4; ct++) {
        int col = col_half * 32 + ct * 8 + 2 * tig;
        float bia0 = b2f[col], bia1 = b2f[col + 1];
        S->wb[rA][col]         = acc2[ct][0] + bia0 + S->xs[rA][col];
        S->wb[rA][col + 1]     = acc2[ct][1] + bia1 + S->xs[rA][col + 1];
        S->wb[rA + 8][col]     = acc2[ct][2] + bia0 + S->xs[rA + 8][col];
        S->wb[rA + 8][col + 1] = acc2[ct][3] + bia1 + S->xs[rA + 8][col + 1];
    }
    __syncthreads();
    #pragma unroll
    for (int rr = 0; rr < 8; rr++) {
        int row = w * 8 + rr;
        float v0 = S->wb[row][lane], v1 = S->wb[row][lane + 32];
        float s = v0 + v1;
        #pragma unroll
        for (int o = 16; o; o >>= 1) s += __shfl_xor_sync(0xffffffffu, s, o);
        float mu = s / 64.f;
        float d0 = v0 - mu, d1 = v1 - mu;
        float vv = d0 * d0 + d1 * d1;
        #pragma unroll
        for (int o = 16; o; o >>= 1) vv += __shfl_xor_sync(0xffffffffu, vv, o);
        float inv = rsqrtf(vv / 64.f + 1e-5f);
        g_z[(r0 + row) * DM + lane]      = d0 * inv * g2[lane]      + bb2[lane];
        g_z[(r0 + row) * DM + lane + 32] = d1 * inv * g2[lane + 32] + bb2[lane + 32];
    }
}

// ---------------- final LN ----------------
__global__ void final_ln_kernel(const float* __restrict__ gf, const float* __restrict__ bf) {
    int t = threadIdx.x, lane = t & 31, w = t >> 5;
    int r = blockIdx.x * 8 + w;
    float v0 = g_z[r * DM + lane], v1 = g_z[r * DM + lane + 32];
    float s = v0 + v1;
    #pragma unroll
    for (int o = 16; o; o >>= 1) s += __shfl_xor_sync(0xffffffffu, s, o);
    float mu = s / 64.f;
    float d0 = v0 - mu, d1 = v1 - mu;
    float vv = d0 * d0 + d1 * d1;
    #pragma unroll
    for (int o = 16; o; o >>= 1) vv += __shfl_xor_sync(0xffffffffu, vv, o);
    float inv = rsqrtf(vv / 64.f + 1e-5f);
    g_z[r * DM + lane]      = d0 * inv * gf[lane]      + bf[lane];
    g_z[r * DM + lane + 32] = d1 * inv * gf[lane + 32] + bf[lane + 32];
}

// ---------------- output projection ----------------
__global__ void proj_partial_kernel(const float* __restrict__ outW) {
    int seg = blockIdx.x;
    int bg  = blockIdx.y;
    __shared__ float zc[8][SEG];
    int t = threadIdx.x, lane = t & 31, w = t >> 5;
    int k0 = seg * SEG;
    for (int i = t; i < 8 * SEG; i += 256) {
        int bmo = i / SEG, kk = i % SEG;
        zc[bmo][kk] = g_z[(bg * 8 + bmo) * KTOT + k0 + kk];
    }
    __syncthreads();
    for (int p = w; p < PRED; p += 8) {
        float acc[8] = {0.f, 0.f, 0.f, 0.f, 0.f, 0.f, 0.f, 0.f};
        for (int kk = lane; kk < SEG; kk += 32) {
            float ww = outW[p * KTOT + k0 + kk];
            #pragma unroll
            for (int bmo = 0; bmo < 8; bmo++) acc[bmo] += ww * zc[bmo][kk];
        }
        #pragma unroll
        for (int bmo = 0; bmo < 8; bmo++) {
            #pragma unroll
            for (int o = 16; o; o >>= 1)
                acc[bmo] += __shfl_xor_sync(0xffffffffu, acc[bmo], o);
        }
        if (lane == 0) {
            #pragma unroll
            for (int bmo = 0; bmo < 8; bmo++)
                g_pp[(p * BM + bg * 8 + bmo) * NSEG + seg] = acc[bmo];
        }
    }
}

__global__ void proj_reduce_kernel(const float* __restrict__ outb, float* __restrict__ out) {
    int i = blockIdx.x * 256 + threadIdx.x;
    if (i >= PRED * BM) return;
    int p = i / BM, bm = i % BM;
    float s = outb[p];
    #pragma unroll
    for (int seg = 0; seg < NSEG; seg++) s += g_pp[(p * BM + bm) * NSEG + seg];
    int b = bm / M_, m = bm % M_;
    out[(b * PRED + p) * M_ + m] = s;
}

// ---------------- launch ----------------
extern "C" void kernel_launch(void* const* d_in, const int* in_sizes, int n_in,
                              void* d_out, int out_size) {
    const float* x_enc = (const float*)d_in[0];
    const float* in_W  = (const float*)d_in[4];
    const float* in_b  = (const float*)d_in[5];
    const float* Wq    = (const float*)d_in[6];
    const float* bq    = (const float*)d_in[7];
    const float* Wk    = (const float*)d_in[8];
    const float* bk    = (const float*)d_in[9];
    const float* Wv    = (const float*)d_in[10];
    const float* bv    = (const float*)d_in[11];
    const float* Wo    = (const float*)d_in[12];
    const float* bo    = (const float*)d_in[13];
    const float* c1_W  = (const float*)d_in[14];
    const float* c1_b  = (const float*)d_in[15];
    const float* c2_W  = (const float*)d_in[16];
    const float* c2_b  = (const float*)d_in[17];
    const float* ln1_g = (const float*)d_in[18];
    const float* ln1_b = (const float*)d_in[19];
    const float* ln2_g = (const float*)d_in[20];
    const float* ln2_b = (const float*)d_in[21];
    const float* lnf_g = (const float*)d_in[22];
    const float* lnf_b = (const float*)d_in[23];
    const float* out_W = (const float*)d_in[24];
    const float* out_b = (const float*)d_in[25];
    float* out = (float*)d_out;

    const int smemG = sizeof(SmemG128);
    const int smemF = sizeof(SmemFFN);
    cudaFuncSetAttribute(qkv_kernel,    cudaFuncAttributeMaxDynamicSharedMemorySize, smemG);
    cudaFuncSetAttribute(wo_ln1_kernel, cudaFuncAttributeMaxDynamicSharedMemorySize, smemG);
    cudaFuncSetAttribute(ffn_ln2_kernel,cudaFuncAttributeMaxDynamicSharedMemorySize, smemF);

    static cudaStream_t s2 = nullptr;
    static cudaEvent_t evFork = nullptr, evIdx = nullptr;
    static cudaEvent_t evQ[2] = {nullptr, nullptr}, evV[2] = {nullptr, nullptr};
    if (s2 == nullptr) {
        cudaStreamCreateWithFlags(&s2, cudaStreamNonBlocking);
        cudaEventCreateWithFlags(&evFork, cudaEventDisableTiming);
        cudaEventCreateWithFlags(&evIdx,  cudaEventDisableTiming);
        for (int e = 0; e < 2; e++) {
            cudaEventCreateWithFlags(&evQ[e], cudaEventDisableTiming);
            cudaEventCreateWithFlags(&evV[e], cudaEventDisableTiming);
        }
    }

    cudaEventRecord(evFork, 0);
    cudaStreamWaitEvent(s2, evFork, 0);

    rand_idx_kernel<<<(2 * NP * UP + 255) / 256, 256, 0, s2>>>();
    cudaEventRecord(evIdx, s2);

    patch_embed_kernel<<<NROW / 16, 256>>>(x_enc, in_W, in_b);
    cudaStreamWaitEvent(0, evIdx, 0);

    for (int e = 0; e < 2; e++) {
        qkv_kernel<<<dim3(256, 3), 256, smemG>>>(Wq + e * DM * DM, bq + e * DM,
                                                 Wk + e * DM * DM, bk + e * DM,
                                                 Wv + e * DM * DM, bv + e * DM);
        cudaEventRecord(evQ[e], 0);

        cudaStreamWaitEvent(s2, evQ[e], 0);
        vmean_kernel<<<BM, 256, 0, s2>>>();
        bcast_kernel<<<NROW * 16 / 256, 256, 0, s2>>>();
        cudaEventRecord(evV[e], s2);

        sparsity_kernel<<<BM * H_, 256>>>(e);
        argmax_kernel<<<BM * H_, 32>>>();

        cudaStreamWaitEvent(0, evV[e], 0);
        attn_dense_kernel<<<BM * H_, 256>>>();
        wo_ln1_kernel<<<256, 256, smemG>>>(Wo + e * DM * DM, bo + e * DM,
                                           ln1_g + e * DM, ln1_b + e * DM);
        ffn_ln2_kernel<<<NROW / 64, 256, smemF>>>(c1_W + e * DFF * DM, c1_b + e * DFF,
                                                  c2_W + e * DM * DFF, c2_b + e * DM,
                                                  ln2_g + e * DM, ln2_b + e * DM);
    }

    final_ln_kernel<<<NROW / 8, 256>>>(lnf_g, lnf_b);
    proj_partial_kernel<<<dim3(NSEG, 8), 256>>>(out_W);
    proj_reduce_kernel<<<(PRED * BM + 255) / 256, 256>>>(out_b, out);
}

// round 17
// speedup vs baseline: 1.3051x; 1.0158x over previous
#include <cuda_runtime.h>
#include <cstdint>
#include <math.h>

#define B_      8
#define M_      8
#define BM      64
#define SL      4096
#define P_      16
#define STRIDE_ 8
#define NP      511
#define DM      64
#define H_      8
#define DH      8
#define DFF     256
#define PRED    96
#define UP      35
#define NROW    (BM*NP)      // 32704
#define KTOT    (NP*DM)      // 32704
#define NSEG    32
#define SEG     1022

// ---------------- scratch ----------------
__device__ float g_z  [NROW*DM];
__device__ float g_q  [NROW*DM];
__device__ float g_k  [NROW*DM];
__device__ float g_v  [NROW*DM];
__device__ float g_ctx[NROW*DM];
__device__ float g_x1 [NROW*DM];
__device__ int   g_idxT[2*UP*NP];        // [e][u][l]
__device__ float g_sp [BM*H_*NP];
__device__ float g_vmean[BM*DM];
__device__ float g_pp [PRED*BM*NSEG];

__device__ __forceinline__ void fma4(float4& o, float s, const float4& b) {
    o.x += s * b.x; o.y += s * b.y; o.z += s * b.z; o.w += s * b.w;
}

// ---------------- tf32 mma helpers ----------------
__device__ __forceinline__ uint32_t tf32cvt(float v) {
    uint32_t r;
    asm("cvt.rna.tf32.f32 %0, %1;" : "=r"(r) : "f"(v));
    return r;
}

__device__ __forceinline__ void mma_tf32(float& c0, float& c1, float& c2, float& c3,
                                         uint32_t a0, uint32_t a1, uint32_t a2, uint32_t a3,
                                         uint32_t b0, uint32_t b1) {
    asm volatile(
        "mma.sync.aligned.m16n8k8.row.col.f32.tf32.tf32.f32 "
        "{%0,%1,%2,%3},{%4,%5,%6,%7},{%8,%9},{%0,%1,%2,%3};"
        : "+f"(c0), "+f"(c1), "+f"(c2), "+f"(c3)
        : "r"(a0), "r"(a1), "r"(a2), "r"(a3), "r"(b0), "r"(b1));
}

// ---------------- threefry2x32 (bitwise JAX-compatible) ----------------
__device__ __forceinline__ uint32_t rotl32(uint32_t v, int r) {
    return (v << r) | (v >> (32 - r));
}

__device__ __forceinline__ void tf2x32(uint32_t k0, uint32_t k1,
                                       uint32_t& x0, uint32_t& x1) {
    uint32_t ks0 = k0, ks1 = k1, ks2 = k0 ^ k1 ^ 0x1BD11BDAu;
    const int ra[4] = {13, 15, 26, 6};
    const int rb[4] = {17, 29, 16, 24};
    x0 += ks0; x1 += ks1;
    #pragma unroll
    for (int i = 0; i < 4; i++) { x0 += x1; x1 = rotl32(x1, ra[i]); x1 ^= x0; }
    x0 += ks1; x1 += ks2 + 1u;
    #pragma unroll
    for (int i = 0; i < 4; i++) { x0 += x1; x1 = rotl32(x1, rb[i]); x1 ^= x0; }
    x0 += ks2; x1 += ks0 + 2u;
    #pragma unroll
    for (int i = 0; i < 4; i++) { x0 += x1; x1 = rotl32(x1, ra[i]); x1 ^= x0; }
    x0 += ks0; x1 += ks1 + 3u;
    #pragma unroll
    for (int i = 0; i < 4; i++) { x0 += x1; x1 = rotl32(x1, rb[i]); x1 ^= x0; }
    x0 += ks1; x1 += ks2 + 4u;
    #pragma unroll
    for (int i = 0; i < 4; i++) { x0 += x1; x1 = rotl32(x1, ra[i]); x1 ^= x0; }
    x0 += ks2; x1 += ks0 + 5u;
}

__device__ __forceinline__ uint32_t rbits17885(uint32_t k0, uint32_t k1, int j) {
    const int HALF = 8943;
    uint32_t x0, x1;
    if (j < HALF) {
        x0 = (uint32_t)j;
        x1 = (j < HALF - 1) ? (uint32_t)(j + HALF) : 0u;
        tf2x32(k0, k1, x0, x1);
        return x0;
    } else {
        x0 = (uint32_t)(j - HALF);
        x1 = (uint32_t)j;
        tf2x32(k0, k1, x0, x1);
        return x1;
    }
}

__global__ void rand_idx_kernel() {
    int j2 = blockIdx.x * blockDim.x + threadIdx.x;
    if (j2 >= 2 * NP * UP) return;
    int e = j2 / (NP * UP);
    int j = j2 % (NP * UP);
    uint32_t f0 = 0u, f1 = (uint32_t)e;
    tf2x32(0u, 1u, f0, f1);
    uint32_t a0 = 0u, a1 = 2u; tf2x32(f0, f1, a0, a1);
    uint32_t b0 = 1u, b1 = 3u; tf2x32(f0, f1, b0, b1);
    uint32_t hi = rbits17885(a0, b0, j);
    uint32_t lo = rbits17885(a1, b1, j);
    uint32_t off = ((hi % 511u) * 32u + (lo % 511u)) % 511u;
    int l = j / UP, u = j % UP;
    g_idxT[e * UP * NP + u * NP + l] = (int)off;
}

// ---------------- patch embedding (coalesced) ----------------
// block = (b, chunk of 16 patch positions). Loads xe[b][n0*8 .. n0*8+136)[8]
// contiguously, emits 8 m-rows x 16 n x 64 c.
__global__ __launch_bounds__(256)
void patch_embed_kernel(const float* __restrict__ xe,
                        const float* __restrict__ inW,
                        const float* __restrict__ inb) {
    __shared__ float ps[136][8];    // [sl - n0*8][m]
    __shared__ float ws[64][17];
    __shared__ float bs[64];
    int t = threadIdx.x;
    int b  = blockIdx.y;
    int n0 = blockIdx.x * 16;
    int sl0 = n0 * STRIDE_;
    // coalesced load: 136*8 = 1088 floats (clamped to SL)
    for (int i = t; i < 136 * 8; i += 256) {
        int sl = sl0 + i / 8;
        ps[i / 8][i % 8] = (sl < SL) ? xe[(b * SL + sl) * M_ + (i % 8)] : 0.f;
    }
    for (int i = t; i < 64 * P_; i += 256) ws[i / P_][i % P_] = inW[i];
    if (t < 64) bs[t] = inb[t];
    __syncthreads();
    int c = t & 63, grp = t >> 6;     // grp 0..3 -> 32 (m,n) pairs each
    #pragma unroll
    for (int i = 0; i < 32; i++) {
        int mn = grp * 32 + i;        // 0..127
        int m = mn >> 4, dn = mn & 15;
        int n = n0 + dn;
        if (n >= NP) continue;
        float acc = bs[c];
        #pragma unroll
        for (int p = 0; p < P_; p++) acc += ws[c][p] * ps[dn * 8 + p][m];
        g_z[((b * M_ + m) * NP + n) * DM + c] = acc;
    }
}

// ---------------- QKV GEMM (tf32 mma) ----------------
struct SmemG128 {
    float As[128][68];
    float Bs[64][68];
};

__global__ __launch_bounds__(256)
void qkv_kernel(const float* __restrict__ Wq, const float* __restrict__ bq,
                const float* __restrict__ Wk, const float* __restrict__ bk,
                const float* __restrict__ Wv, const float* __restrict__ bv) {
    extern __shared__ char smem_raw[];
    SmemG128* S = (SmemG128*)smem_raw;
    int t = threadIdx.x;
    int r0 = blockIdx.x * 128;
    int rows = NROW - r0; if (rows > 128) rows = 128;
    const float* W; const float* bias; float* out;
    if (blockIdx.y == 0)      { W = Wq; bias = bq; out = g_q; }
    else if (blockIdx.y == 1) { W = Wk; bias = bk; out = g_k; }
    else                      { W = Wv; bias = bv; out = g_v; }

    for (int i = t; i < 128 * 16; i += 256) {
        int row = i / 16, f4 = i % 16;
        float4 v = make_float4(0.f, 0.f, 0.f, 0.f);
        if (row < rows) v = *(const float4*)&g_z[(r0 + row) * DM + f4 * 4];
        *(float4*)&S->As[row][f4 * 4] = v;
    }
    {
        int c = t >> 2, ks0 = (t & 3) * 16;
        #pragma unroll
        for (int q = 0; q < 4; q++) {
            float4 wv = *(const float4*)&W[c * 64 + ks0 + q * 4];
            S->Bs[ks0 + q * 4 + 0][c] = wv.x;
            S->Bs[ks0 + q * 4 + 1][c] = wv.y;
            S->Bs[ks0 + q * 4 + 2][c] = wv.z;
            S->Bs[ks0 + q * 4 + 3][c] = wv.w;
        }
    }
    __syncthreads();

    int lane = t & 31, w = t >> 5;
    int gid = lane >> 2, tig = lane & 3;
    int rA = w * 16 + gid;

    float acc[8][4];
    #pragma unroll
    for (int ct = 0; ct < 8; ct++)
        acc[ct][0] = acc[ct][1] = acc[ct][2] = acc[ct][3] = 0.f;

    #pragma unroll
    for (int kt = 0; kt < 8; kt++) {
        int k0 = kt * 8;
        uint32_t a0 = tf32cvt(S->As[rA][k0 + tig]);
        uint32_t a1 = tf32cvt(S->As[rA + 8][k0 + tig]);
        uint32_t a2 = tf32cvt(S->As[rA][k0 + tig + 4]);
        uint32_t a3 = tf32cvt(S->As[rA + 8][k0 + tig + 4]);
        #pragma unroll
        for (int ct = 0; ct < 8; ct++) {
            int col = ct * 8;
            uint32_t b0 = tf32cvt(S->Bs[k0 + tig][col + gid]);
            uint32_t b1 = tf32cvt(S->Bs[k0 + tig + 4][col + gid]);
            mma_tf32(acc[ct][0], acc[ct][1], acc[ct][2], acc[ct][3],
                     a0, a1, a2, a3, b0, b1);
        }
    }

    #pragma unroll
    for (int ct = 0; ct < 8; ct++) {
        int col = ct * 8 + 2 * tig;
        float bia0 = bias[col], bia1 = bias[col + 1];
        if (rA < rows)
            *(float2*)&out[(r0 + rA) * DM + col] =
                make_float2(acc[ct][0] + bia0, acc[ct][1] + bia1);
        if (rA + 8 < rows)
            *(float2*)&out[(r0 + rA + 8) * DM + col] =
                make_float2(acc[ct][2] + bia0, acc[ct][3] + bia1);
    }
}

// ---------------- V mean per bm ----------------
__global__ __launch_bounds__(256)
void vmean_kernel() {
    __shared__ float part[4][64];
    int bm = blockIdx.x;
    int t = threadIdx.x;
    int col = t & 63, slice = t >> 6;
    float s = 0.f;
    for (int l = slice; l < NP; l += 4) s += g_v[(bm * NP + l) * DM + col];
    part[slice][col] = s;
    __syncthreads();
    if (t < 64) {
        float v = (part[0][t] + part[1][t] + part[2][t] + part[3][t]) / (float)NP;
        g_vmean[bm * DM + t] = v;
    }
}

// ---------------- broadcast vmean into g_ctx ----------------
__global__ __launch_bounds__(256)
void bcast_kernel() {
    int i = blockIdx.x * 256 + threadIdx.x;
    int row = i >> 4, f4 = i & 15;
    int bm = row / NP;
    ((float4*)g_ctx)[i] = ((const float4*)g_vmean)[bm * 16 + f4];
}

// ---------------- sparsity scores ----------------
__global__ __launch_bounds__(256)
void sparsity_kernel(int e) {
    __shared__ float4 klo[NP];
    __shared__ float4 khi[NP];
    int bh = blockIdx.x;
    int bm = bh / H_, h = bh % H_;
    int t = threadIdx.x;
    long rbase = (long)bm * NP;
    const int* idxT = g_idxT + e * UP * NP;

    const float4* gk4 = (const float4*)g_k;
    const float4* gq4 = (const float4*)g_q;
    for (int i = t; i < NP * 2; i += 256) {
        int l = i >> 1, half = i & 1;
        float4 v = gk4[(rbase + l) * 16 + h * 2 + half];
        if (half == 0) klo[l] = v; else khi[l] = v;
    }
    __syncthreads();

    for (int l = t; l < NP; l += 256) {
        long qb = (rbase + l) * 16 + h * 2;
        float4 q0 = gq4[qb], q1 = gq4[qb + 1];
        float mx = -INFINITY, sm = 0.f;
        #pragma unroll 7
        for (int u = 0; u < UP; u++) {
            int j = idxT[u * NP + l];
            float4 k0 = klo[j];
            float4 k1 = khi[j];
            float dot = q0.x*k0.x + q0.y*k0.y + q0.z*k0.z + q0.w*k0.w
                      + q1.x*k1.x + q1.y*k1.y + q1.z*k1.z + q1.w*k1.w;
            mx = fmaxf(mx, dot);
            sm += dot;
        }
        g_sp[bh * NP + l] = mx - sm / (float)NP;
    }
}

// ---------------- dense attention (fused argmax + online softmax) ---------
__global__ __launch_bounds__(256)
void attn_dense_kernel() {
    __shared__ float4 klo[NP];
    __shared__ float4 khi[NP];
    __shared__ float4 vlo[NP];
    __shared__ float4 vhi[NP];
    __shared__ int   top[UP];
    int bm = blockIdx.x / H_, h = blockIdx.x % H_;
    int t = threadIdx.x, lane = t & 31, w = t >> 5;
    long rbase = (long)bm * NP;

    const float4* gk4 = (const float4*)g_k;
    const float4* gv4 = (const float4*)g_v;
    const float4* gq4 = (const float4*)g_q;

    if (w == 0) {
        // warp 0: register top-35 from g_sp (tie-break smaller index),
        // overlapped with K/V smem fill by warps 1-7
        const float* sp = g_sp + blockIdx.x * NP;
        float vals[16];
        #pragma unroll
        for (int jj = 0; jj < 16; jj++) {
            int l = lane + 32 * jj;
            vals[jj] = (l < NP) ? sp[l] : -INFINITY;
        }
        for (int it = 0; it < UP; it++) {
            float bv = -INFINITY; int bi = NP;
            #pragma unroll
            for (int jj = 0; jj < 16; jj++) {
                float v = vals[jj];
                if (v > bv) { bv = v; bi = lane + 32 * jj; }
            }
            #pragma unroll
            for (int off = 16; off; off >>= 1) {
                float ov = __shfl_xor_sync(0xffffffffu, bv, off);
                int   oi = __shfl_xor_sync(0xffffffffu, bi, off);
                if (ov > bv || (ov == bv && oi < bi)) { bv = ov; bi = oi; }
            }
            if (lane == 0) top[it] = bi;
            if ((bi & 31) == lane) {
                int tgt = bi >> 5;
                #pragma unroll
                for (int jj = 0; jj < 16; jj++)
                    if (jj == tgt) vals[jj] = -INFINITY;
            }
        }
    } else {
        for (int i = t - 32; i < NP * 2; i += 224) {
            int l = i >> 1, half = i & 1;
            long src = (rbase + l) * 16 + h * 2 + half;
            float4 kv = gk4[src];
            float4 vv = gv4[src];
            if (half == 0) { klo[l] = kv; vlo[l] = vv; }
            else           { khi[l] = kv; vhi[l] = vv; }
        }
    }
    __syncthreads();

    float4* gc4 = (float4*)g_ctx;
    const float scale = 0.35355339059327373f;
    for (int i = w; i < UP; i += 8) {
        int l = top[i];
        long qb = (rbase + l) * 16 + h * 2;
        float4 q0 = gq4[qb], q1 = gq4[qb + 1];
        float m = -INFINITY, sum = 0.f;
        float4 a0 = make_float4(0.f, 0.f, 0.f, 0.f);
        float4 a1 = make_float4(0.f, 0.f, 0.f, 0.f);
        #pragma unroll 4
        for (int jj = 0; jj < 16; jj++) {
            int j = lane + 32 * jj;
            float s;
            if (j < NP) {
                float4 k0 = klo[j];
                float4 k1 = khi[j];
                s = (q0.x*k0.x + q0.y*k0.y + q0.z*k0.z + q0.w*k0.w
                   + q1.x*k1.x + q1.y*k1.y + q1.z*k1.z + q1.w*k1.w) * scale;
            } else s = -INFINITY;
            float mn = fmaxf(m, s);
            float corr = __expf(m - mn);
            float p    = __expf(s - mn);
            sum = sum * corr + p;
            if (j < NP) {
                float4 v0 = vlo[j];
                float4 v1 = vhi[j];
                a0.x = a0.x * corr + p * v0.x; a0.y = a0.y * corr + p * v0.y;
                a0.z = a0.z * corr + p * v0.z; a0.w = a0.w * corr + p * v0.w;
                a1.x = a1.x * corr + p * v1.x; a1.y = a1.y * corr + p * v1.y;
                a1.z = a1.z * corr + p * v1.z; a1.w = a1.w * corr + p * v1.w;
            } else {
                a0.x *= corr; a0.y *= corr; a0.z *= corr; a0.w *= corr;
                a1.x *= corr; a1.y *= corr; a1.z *= corr; a1.w *= corr;
            }
            m = mn;
        }
        float M = m;
        #pragma unroll
        for (int off = 16; off; off >>= 1)
            M = fmaxf(M, __shfl_xor_sync(0xffffffffu, M, off));
        float c = __expf(m - M);
        sum *= c;
        a0.x *= c; a0.y *= c; a0.z *= c; a0.w *= c;
        a1.x *= c; a1.y *= c; a1.z *= c; a1.w *= c;
        #pragma unroll
        for (int off = 16; off; off >>= 1) {
            sum  += __shfl_xor_sync(0xffffffffu, sum, off);
            a0.x += __shfl_xor_sync(0xffffffffu, a0.x, off);
            a0.y += __shfl_xor_sync(0xffffffffu, a0.y, off);
            a0.z += __shfl_xor_sync(0xffffffffu, a0.z, off);
            a0.w += __shfl_xor_sync(0xffffffffu, a0.w, off);
            a1.x += __shfl_xor_sync(0xffffffffu, a1.x, off);
            a1.y += __shfl_xor_sync(0xffffffffu, a1.y, off);
            a1.z += __shfl_xor_sync(0xffffffffu, a1.z, off);
            a1.w += __shfl_xor_sync(0xffffffffu, a1.w, off);
        }
        if (lane == 0) {
            float inv = 1.f / sum;
            gc4[qb]     = make_float4(a0.x*inv, a0.y*inv, a0.z*inv, a0.w*inv);
            gc4[qb + 1] = make_float4(a1.x*inv, a1.y*inv, a1.z*inv, a1.w*inv);
        }
    }
}

// ---------------- Wo GEMM + residual + LN1 (tf32 mma) ----------------
__global__ __launch_bounds__(256)
void wo_ln1_kernel(const float* __restrict__ Wo, const float* __restrict__ bo,
                   const float* __restrict__ g1, const float* __restrict__ b1) {
    extern __shared__ char smem_raw[];
    SmemG128* S = (SmemG128*)smem_raw;
    int t = threadIdx.x;
    int r0 = blockIdx.x * 128;
    int rows = NROW - r0; if (rows > 128) rows = 128;

    for (int i = t; i < 128 * 16; i += 256) {
        int row = i / 16, f4 = i % 16;
        float4 v = make_float4(0.f, 0.f, 0.f, 0.f);
        if (row < rows) v = *(const float4*)&g_ctx[(r0 + row) * DM + f4 * 4];
        *(float4*)&S->As[row][f4 * 4] = v;
    }
    {
        int c = t >> 2, ks0 = (t & 3) * 16;
        #pragma unroll
        for (int q = 0; q < 4; q++) {
            float4 wv = *(const float4*)&Wo[c * 64 + ks0 + q * 4];
            S->Bs[ks0 + q * 4 + 0][c] = wv.x;
            S->Bs[ks0 + q * 4 + 1][c] = wv.y;
            S->Bs[ks0 + q * 4 + 2][c] = wv.z;
            S->Bs[ks0 + q * 4 + 3][c] = wv.w;
        }
    }
    __syncthreads();

    int lane = t & 31, w = t >> 5;
    int gid = lane >> 2, tig = lane & 3;
    int rA = w * 16 + gid;

    float acc[8][4];
    #pragma unroll
    for (int ct = 0; ct < 8; ct++)
        acc[ct][0] = acc[ct][1] = acc[ct][2] = acc[ct][3] = 0.f;

    #pragma unroll
    for (int kt = 0; kt < 8; kt++) {
        int k0 = kt * 8;
        uint32_t a0 = tf32cvt(S->As[rA][k0 + tig]);
        uint32_t a1 = tf32cvt(S->As[rA + 8][k0 + tig]);
        uint32_t a2 = tf32cvt(S->As[rA][k0 + tig + 4]);
        uint32_t a3 = tf32cvt(S->As[rA + 8][k0 + tig + 4]);
        #pragma unroll
        for (int ct = 0; ct < 8; ct++) {
            int col = ct * 8;
            uint32_t b0 = tf32cvt(S->Bs[k0 + tig][col + gid]);
            uint32_t b1 = tf32cvt(S->Bs[k0 + tig + 4][col + gid]);
            mma_tf32(acc[ct][0], acc[ct][1], acc[ct][2], acc[ct][3],
                     a0, a1, a2, a3, b0, b1);
        }
    }

    __syncthreads();
    #pragma unroll
    for (int ct = 0; ct < 8; ct++) {
        int col = ct * 8 + 2 * tig;
        float bia0 = bo[col], bia1 = bo[col + 1];
        if (rA < rows) {
            float2 z = *(const float2*)&g_z[(r0 + rA) * DM + col];
            S->As[rA][col]     = acc[ct][0] + bia0 + z.x;
            S->As[rA][col + 1] = acc[ct][1] + bia1 + z.y;
        }
        if (rA + 8 < rows) {
            float2 z = *(const float2*)&g_z[(r0 + rA + 8) * DM + col];
            S->As[rA + 8][col]     = acc[ct][2] + bia0 + z.x;
            S->As[rA + 8][col + 1] = acc[ct][3] + bia1 + z.y;
        }
    }
    __syncthreads();
    for (int rr = 0; rr < 16; rr++) {
        int row = w * 16 + rr;
        if (row >= rows) break;
        float v0 = S->As[row][lane], v1 = S->As[row][lane + 32];
        float s = v0 + v1;
        #pragma unroll
        for (int o = 16; o; o >>= 1) s += __shfl_xor_sync(0xffffffffu, s, o);
        float mu = s / 64.f;
        float d0 = v0 - mu, d1 = v1 - mu;
        float vv = d0 * d0 + d1 * d1;
        #pragma unroll
        for (int o = 16; o; o >>= 1) vv += __shfl_xor_sync(0xffffffffu, vv, o);
        float inv = rsqrtf(vv / 64.f + 1e-5f);
        g_x1[(r0 + row) * DM + lane]      = d0 * inv * g1[lane]      + b1[lane];
        g_x1[(r0 + row) * DM + lane + 32] = d1 * inv * g1[lane + 32] + b1[lane + 32];
    }
}

// ---------------- fused FFN + residual + LN2 (+ optional final LN) --------
struct SmemFFN {
    float xs[64][68];
    float wb[64][68];
    float ys[64][260];
};

__global__ __launch_bounds__(256)
void ffn_ln2_kernel(const float* __restrict__ W1, const float* __restrict__ b1f,
                    const float* __restrict__ W2, const float* __restrict__ b2f,
                    const float* __restrict__ g2, const float* __restrict__ bb2,
                    const float* __restrict__ gf, const float* __restrict__ bf,
                    int last) {
    extern __shared__ char smem_raw[];
    SmemFFN* S = (SmemFFN*)smem_raw;
    int t = threadIdx.x;
    int r0 = blockIdx.x * 64;
    int lane = t & 31, w = t >> 5;
    int gid = lane >> 2, tig = lane & 3;
    int row_tile = w >> 1;
    int col_half = w & 1;
    int rA = row_tile * 16 + gid;
    int cw = t >> 2, ks0 = (t & 3) * 16;

    for (int i = t; i < 64 * 16; i += 256) {
        int row = i / 16, f4 = i % 16;
        *(float4*)&S->xs[row][f4 * 4] = *(const float4*)&g_x1[(r0 + row) * DM + f4 * 4];
    }

    for (int cc = 0; cc < 4; cc++) {
        __syncthreads();
        #pragma unroll
        for (int q = 0; q < 4; q++) {
            float4 wv = *(const float4*)&W1[(cc * 64 + cw) * 64 + ks0 + q * 4];
            S->wb[ks0 + q * 4 + 0][cw] = wv.x;
            S->wb[ks0 + q * 4 + 1][cw] = wv.y;
            S->wb[ks0 + q * 4 + 2][cw] = wv.z;
            S->wb[ks0 + q * 4 + 3][cw] = wv.w;
        }
        __syncthreads();
        float acc[4][4];
        #pragma unroll
        for (int ct = 0; ct < 4; ct++)
            acc[ct][0] = acc[ct][1] = acc[ct][2] = acc[ct][3] = 0.f;
        #pragma unroll
        for (int kt = 0; kt < 8; kt++) {
            int k0 = kt * 8;
            uint32_t a0 = tf32cvt(S->xs[rA][k0 + tig]);
            uint32_t a1 = tf32cvt(S->xs[rA + 8][k0 + tig]);
            uint32_t a2 = tf32cvt(S->xs[rA][k0 + tig + 4]);
            uint32_t a3 = tf32cvt(S->xs[rA + 8][k0 + tig + 4]);
            #pragma unroll
            for (int ct = 0; ct < 4; ct++) {
                int col = col_half * 32 + ct * 8;
                uint32_t b0 = tf32cvt(S->wb[k0 + tig][col + gid]);
                uint32_t b1 = tf32cvt(S->wb[k0 + tig + 4][col + gid]);
                mma_tf32(acc[ct][0], acc[ct][1], acc[ct][2], acc[ct][3],
                         a0, a1, a2, a3, b0, b1);
            }
        }
        #pragma unroll
        for (int ct = 0; ct < 4; ct++) {
            int colg = cc * 64 + col_half * 32 + ct * 8 + 2 * tig;
            float bia0 = b1f[colg], bia1 = b1f[colg + 1];
            float x0 = acc[ct][0] + bia0, x1 = acc[ct][1] + bia1;
            float x2 = acc[ct][2] + bia0, x3 = acc[ct][3] + bia1;
            S->ys[rA][colg]         = x0 * 0.5f * (1.f + erff(x0 * 0.7071067811865476f));
            S->ys[rA][colg + 1]     = x1 * 0.5f * (1.f + erff(x1 * 0.7071067811865476f));
            S->ys[rA + 8][colg]     = x2 * 0.5f * (1.f + erff(x2 * 0.7071067811865476f));
            S->ys[rA + 8][colg + 1] = x3 * 0.5f * (1.f + erff(x3 * 0.7071067811865476f));
        }
    }

    float acc2[4][4];
    #pragma unroll
    for (int ct = 0; ct < 4; ct++)
        acc2[ct][0] = acc2[ct][1] = acc2[ct][2] = acc2[ct][3] = 0.f;
    for (int kc = 0; kc < 4; kc++) {
        __syncthreads();
        #pragma unroll
        for (int q = 0; q < 4; q++) {
            float4 wv = *(const float4*)&W2[cw * 256 + kc * 64 + ks0 + q * 4];
            S->wb[ks0 + q * 4 + 0][cw] = wv.x;
            S->wb[ks0 + q * 4 + 1][cw] = wv.y;
            S->wb[ks0 + q * 4 + 2][cw] = wv.z;
            S->wb[ks0 + q * 4 + 3][cw] = wv.w;
        }
        __syncthreads();
        #pragma unroll
        for (int kt = 0; kt < 8; kt++) {
            int k0 = kt * 8;
            int kg = kc * 64 + k0;
            uint32_t a0 = tf32cvt(S->ys[rA][kg + tig]);
            uint32_t a1 = tf32cvt(S->ys[rA + 8][kg + tig]);
            uint32_t a2 = tf32cvt(S->ys[rA][kg + tig + 4]);
            uint32_t a3 = tf32cvt(S->ys[rA + 8][kg + tig + 4]);
            #pragma unroll
            for (int ct = 0; ct < 4; ct++) {
                int col = col_half * 32 + ct * 8;
                uint32_t b0 = tf32cvt(S->wb[k0 + tig][col + gid]);
                uint32_t b1 = tf32cvt(S->wb[k0 + tig + 4][col + gid]);
                mma_tf32(acc2[ct][0], acc2[ct][1], acc2[ct][2], acc2[ct][3],
                         a0, a1, a2, a3, b0, b1);
            }
        }
    }
    __syncthreads();
    #pragma unroll
    for (int ct = 0; ct < 4; ct++) {
        int col = col_half * 32 + ct * 8 + 2 * tig;
        float bia0 = b2f[col], bia1 = b2f[col + 1];
        S->wb[rA][col]         = acc2[ct][0] + bia0 + S->xs[rA][col];
        S->wb[rA][col + 1]     = acc2[ct][1] + bia1 + S->xs[rA][col + 1];
        S->wb[rA + 8][col]     = acc2[ct][2] + bia0 + S->xs[rA + 8][col];
        S->wb[rA + 8][col + 1] = acc2[ct][3] + bia1 + S->xs[rA + 8][col + 1];
    }
    __syncthreads();
    #pragma unroll
    for (int rr = 0; rr < 8; rr++) {
        int row = w * 8 + rr;
        float v0 = S->wb[row][lane], v1 = S->wb[row][lane + 32];
        float s = v0 + v1;
        #pragma unroll
        for (int o = 16; o; o >>= 1) s += __shfl_xor_sync(0xffffffffu, s, o);
        float mu = s / 64.f;
        float d0 = v0 - mu, d1 = v1 - mu;
        float vv = d0 * d0 + d1 * d1;
        #pragma unroll
        for (int o = 16; o; o >>= 1) vv += __shfl_xor_sync(0xffffffffu, vv, o);
        float inv = rsqrtf(vv / 64.f + 1e-5f);
        float y0 = d0 * inv * g2[lane]      + bb2[lane];
        float y1 = d1 * inv * g2[lane + 32] + bb2[lane + 32];
        if (last) {
            // final LN fused
            float s2 = y0 + y1;
            #pragma unroll
            for (int o = 16; o; o >>= 1) s2 += __shfl_xor_sync(0xffffffffu, s2, o);
            float mu2 = s2 / 64.f;
            float e0 = y0 - mu2, e1 = y1 - mu2;
            float vv2 = e0 * e0 + e1 * e1;
            #pragma unroll
            for (int o = 16; o; o >>= 1) vv2 += __shfl_xor_sync(0xffffffffu, vv2, o);
            float inv2 = rsqrtf(vv2 / 64.f + 1e-5f);
            y0 = e0 * inv2 * gf[lane]      + bf[lane];
            y1 = e1 * inv2 * gf[lane + 32] + bf[lane + 32];
        }
        g_z[(r0 + row) * DM + lane]      = y0;
        g_z[(r0 + row) * DM + lane + 32] = y1;
    }
}

// ---------------- output projection ----------------
__global__ void proj_partial_kernel(const float* __restrict__ outW) {
    int seg = blockIdx.x;
    int bg  = blockIdx.y;
    __shared__ float zc[8][SEG];
    int t = threadIdx.x, lane = t & 31, w = t >> 5;
    int k0 = seg * SEG;
    for (int i = t; i < 8 * SEG; i += 256) {
        int bmo = i / SEG, kk = i % SEG;
        zc[bmo][kk] = g_z[(bg * 8 + bmo) * KTOT + k0 + kk];
    }
    __syncthreads();
    for (int p = w; p < PRED; p += 8) {
        float acc[8] = {0.f, 0.f, 0.f, 0.f, 0.f, 0.f, 0.f, 0.f};
        for (int kk = lane; kk < SEG; kk += 32) {
            float ww = outW[p * KTOT + k0 + kk];
            #pragma unroll
            for (int bmo = 0; bmo < 8; bmo++) acc[bmo] += ww * zc[bmo][kk];
        }
        #pragma unroll
        for (int bmo = 0; bmo < 8; bmo++) {
            #pragma unroll
            for (int o = 16; o; o >>= 1)
                acc[bmo] += __shfl_xor_sync(0xffffffffu, acc[bmo], o);
        }
        if (lane == 0) {
            #pragma unroll
            for (int bmo = 0; bmo < 8; bmo++)
                g_pp[(p * BM + bg * 8 + bmo) * NSEG + seg] = acc[bmo];
        }
    }
}

__global__ void proj_reduce_kernel(const float* __restrict__ outb, float* __restrict__ out) {
    int i = blockIdx.x * 256 + threadIdx.x;
    if (i >= PRED * BM) return;
    int p = i / BM, bm = i % BM;
    float s = outb[p];
    #pragma unroll
    for (int seg = 0; seg < NSEG; seg++) s += g_pp[(p * BM + bm) * NSEG + seg];
    int b = bm / M_, m = bm % M_;
    out[(b * PRED + p) * M_ + m] = s;
}

// ---------------- launch ----------------
extern "C" void kernel_launch(void* const* d_in, const int* in_sizes, int n_in,
                              void* d_out, int out_size) {
    const float* x_enc = (const float*)d_in[0];
    const float* in_W  = (const float*)d_in[4];
    const float* in_b  = (const float*)d_in[5];
    const float* Wq    = (const float*)d_in[6];
    const float* bq    = (const float*)d_in[7];
    const float* Wk    = (const float*)d_in[8];
    const float* bk    = (const float*)d_in[9];
    const float* Wv    = (const float*)d_in[10];
    const float* bv    = (const float*)d_in[11];
    const float* Wo    = (const float*)d_in[12];
    const float* bo    = (const float*)d_in[13];
    const float* c1_W  = (const float*)d_in[14];
    const float* c1_b  = (const float*)d_in[15];
    const float* c2_W  = (const float*)d_in[16];
    const float* c2_b  = (const float*)d_in[17];
    const float* ln1_g = (const float*)d_in[18];
    const float* ln1_b = (const float*)d_in[19];
    const float* ln2_g = (const float*)d_in[20];
    const float* ln2_b = (const float*)d_in[21];
    const float* lnf_g = (const float*)d_in[22];
    const float* lnf_b = (const float*)d_in[23];
    const float* out_W = (const float*)d_in[24];
    const float* out_b = (const float*)d_in[25];
    float* out = (float*)d_out;

    const int smemG = sizeof(SmemG128);
    const int smemF = sizeof(SmemFFN);
    cudaFuncSetAttribute(qkv_kernel,    cudaFuncAttributeMaxDynamicSharedMemorySize, smemG);
    cudaFuncSetAttribute(wo_ln1_kernel, cudaFuncAttributeMaxDynamicSharedMemorySize, smemG);
    cudaFuncSetAttribute(ffn_ln2_kernel,cudaFuncAttributeMaxDynamicSharedMemorySize, smemF);

    static cudaStream_t s2 = nullptr;
    static cudaEvent_t evFork = nullptr, evIdx = nullptr;
    static cudaEvent_t evQ[2] = {nullptr, nullptr}, evV[2] = {nullptr, nullptr};
    if (s2 == nullptr) {
        cudaStreamCreateWithFlags(&s2, cudaStreamNonBlocking);
        cudaEventCreateWithFlags(&evFork, cudaEventDisableTiming);
        cudaEventCreateWithFlags(&evIdx,  cudaEventDisableTiming);
        for (int e = 0; e < 2; e++) {
            cudaEventCreateWithFlags(&evQ[e], cudaEventDisableTiming);
            cudaEventCreateWithFlags(&evV[e], cudaEventDisableTiming);
        }
    }

    cudaEventRecord(evFork, 0);
    cudaStreamWaitEvent(s2, evFork, 0);

    rand_idx_kernel<<<(2 * NP * UP + 255) / 256, 256, 0, s2>>>();
    cudaEventRecord(evIdx, s2);

    patch_embed_kernel<<<dim3(32, B_), 256>>>(x_enc, in_W, in_b);
    cudaStreamWaitEvent(0, evIdx, 0);

    for (int e = 0; e < 2; e++) {
        qkv_kernel<<<dim3(256, 3), 256, smemG>>>(Wq + e * DM * DM, bq + e * DM,
                                                 Wk + e * DM * DM, bk + e * DM,
                                                 Wv + e * DM * DM, bv + e * DM);
        cudaEventRecord(evQ[e], 0);

        cudaStreamWaitEvent(s2, evQ[e], 0);
        vmean_kernel<<<BM, 256, 0, s2>>>();
        bcast_kernel<<<NROW * 16 / 256, 256, 0, s2>>>();
        cudaEventRecord(evV[e], s2);

        sparsity_kernel<<<BM * H_, 256>>>(e);

        cudaStreamWaitEvent(0, evV[e], 0);
        attn_dense_kernel<<<BM * H_, 256>>>();
        wo_ln1_kernel<<<256, 256, smemG>>>(Wo + e * DM * DM, bo + e * DM,
                                           ln1_g + e * DM, ln1_b + e * DM);
        ffn_ln2_kernel<<<NROW / 64, 256, smemF>>>(c1_W + e * DFF * DM, c1_b + e * DFF,
                                                  c2_W + e * DM * DFF, c2_b + e * DM,
                                                  ln2_g + e * DM, ln2_b + e * DM,
                                                  lnf_g, lnf_b, e == 1);
    }

    proj_partial_kernel<<<dim3(NSEG, 8), 256>>>(out_W);
    proj_reduce_kernel<<<(PRED * BM + 255) / 256, 256>>>(out_b, out);
}